// round 13
// baseline (speedup 1.0000x reference)
#include <cuda_runtime.h>
#include <cstdint>

#define BATCH 8
#define N_PTS 16384
#define M_PTS 1024
#define KS    32
#define CFEAT 64

#define NPREP 140     // prep/ball CTAs in the fused launch

// ---- output layout (float32): [new_xyz | new_features | indices] ----
#define OUT_XYZ_OFF  0
#define OUT_FEAT_OFF (BATCH * M_PTS * 3)                       // 24576
#define OUT_IDX_OFF  (OUT_FEAT_OFF + BATCH * 256 * M_PTS)      // 2121728

// ---- device scratch ----
__device__ float g_xyzT[BATCH][3][N_PTS];
__device__ float g_featT[BATCH][N_PTS][CFEAT];
__device__ float g_Wt0[72 * 64];            // tf32-rounded at prep
__device__ float g_Wt1[64 * 128];           // tf32-rounded at prep
__device__ float g_Wt2[128 * 256];          // tf32-rounded at prep
__device__ int   g_ball[BATCH][M_PTS][KS];
__device__ float g_center[BATCH][M_PTS][3];

// producer->consumer state (reset every launch)
__device__ unsigned g_fps_progress[BATCH];
__device__ unsigned g_prep_done;

// exact (non-FMA) squared distance, left-to-right sum — must match XLA
__device__ __forceinline__ float sqdist(float dx, float dy, float dz) {
    float d = __fmul_rn(dx, dx);
    d = __fadd_rn(d, __fmul_rn(dy, dy));
    d = __fadd_rn(d, __fmul_rn(dz, dz));
    return d;
}

// ---- packed f32x2 helpers (per-lane IEEE rn, bit-identical to scalar) ----
__device__ __forceinline__ unsigned long long pk2(float a, float b) {
    unsigned long long r;
    asm("mov.b64 %0, {%1, %2};" : "=l"(r) : "f"(a), "f"(b));
    return r;
}
__device__ __forceinline__ void upk2(unsigned long long v, float& a, float& b) {
    asm("mov.b64 {%0, %1}, %2;" : "=f"(a), "=f"(b) : "l"(v));
}
__device__ __forceinline__ unsigned long long add2(unsigned long long a, unsigned long long b) {
    unsigned long long r;
    asm("add.rn.f32x2 %0, %1, %2;" : "=l"(r) : "l"(a), "l"(b));
    return r;
}
__device__ __forceinline__ unsigned long long mul2(unsigned long long a, unsigned long long b) {
    unsigned long long r;
    asm("mul.rn.f32x2 %0, %1, %2;" : "=l"(r) : "l"(a), "l"(b));
    return r;
}

// ---- tf32 helpers ----
__device__ __forceinline__ float to_tf32(float x) {
    uint32_t u;
    asm("cvt.rna.tf32.f32 %0, %1;" : "=r"(u) : "f"(x));
    return __uint_as_float(u);
}
__device__ __forceinline__ void mma_tf32(float* d, const uint32_t* a, const uint32_t* b) {
    asm volatile(
        "mma.sync.aligned.m16n8k8.row.col.f32.tf32.tf32.f32 "
        "{%0,%1,%2,%3}, {%4,%5,%6,%7}, {%8,%9}, {%0,%1,%2,%3};"
        : "+f"(d[0]), "+f"(d[1]), "+f"(d[2]), "+f"(d[3])
        : "r"(a[0]), "r"(a[1]), "r"(a[2]), "r"(a[3]), "r"(b[0]), "r"(b[1]));
}

// ---- release/acquire ----
__device__ __forceinline__ void st_release_u32(unsigned* p, unsigned v) {
    asm volatile("st.release.gpu.global.u32 [%0], %1;" :: "l"(p), "r"(v) : "memory");
}
__device__ __forceinline__ unsigned ld_acquire_u32(const unsigned* p) {
    unsigned v;
    asm volatile("ld.acquire.gpu.global.u32 %0, [%1];" : "=r"(v) : "l"(p) : "memory");
    return v;
}

// ======================= reset (graph-replay safety) =======================
__global__ void reset_kernel() {
    if (threadIdx.x < BATCH) g_fps_progress[threadIdx.x] = 0u;
    if (threadIdx.x == BATCH) g_prep_done = 0u;
}

// ======================= fused FPS + prep + ball =======================
// CTAs 0..7: FPS (publishes per-iteration progress).
// CTAs 8..147: prep, then ball queries consuming centroids as they appear.
__global__ __launch_bounds__(1024, 1) void fps_prep_kernel(
    const float* __restrict__ xyz, const float* __restrict__ feat,
    const float* __restrict__ W0, const float* __restrict__ W1,
    const float* __restrict__ W2, float* __restrict__ out)
{
    extern __shared__ float sm[];

    if (blockIdx.x >= BATCH) {
        // ---------------- prep branch ----------------
        const int gtid   = (blockIdx.x - BATCH) * 1024 + threadIdx.x;
        const int stride = NPREP * 1024;

        for (int id = gtid; id < 72 * 64 + 64 * 128 + 128 * 256; id += stride) {
            if (id < 72 * 64) {
                int c = id >> 6, o = id & 63;
                g_Wt0[id] = (c < 67) ? to_tf32(W0[o * 67 + c]) : 0.0f;
            } else if (id < 72 * 64 + 64 * 128) {
                int e = id - 72 * 64;
                int c = e >> 7, o = e & 127;
                g_Wt1[e] = to_tf32(W1[o * 64 + c]);
            } else {
                int e = id - 72 * 64 - 64 * 128;
                int c = e >> 8, o = e & 255;
                g_Wt2[e] = to_tf32(W2[o * 128 + c]);
            }
        }
        for (int id = gtid; id < BATCH * 3 * N_PTS; id += stride) {
            int b = id / (3 * N_PTS);
            int r = id % (3 * N_PTS);
            int c = r / N_PTS;
            int n = r % N_PTS;
            g_xyzT[b][c][n] = xyz[(b * N_PTS + n) * 3 + c];
        }
        const float4* f4 = (const float4*)feat;
        for (int id = gtid; id < (BATCH * CFEAT * N_PTS) / 4; id += stride) {
            float4 v = f4[id];
            int lin = id * 4;
            int b = lin >> 20;
            int r = lin & 0xFFFFF;
            int c = r >> 14;
            int n = r & 16383;
            g_featT[b][n + 0][c] = v.x;
            g_featT[b][n + 1][c] = v.y;
            g_featT[b][n + 2][c] = v.z;
            g_featT[b][n + 3][c] = v.w;
        }

        // signal this CTA's prep complete; wait for all prep CTAs
        __syncthreads();
        if (threadIdx.x == 0) {
            __threadfence();
            atomicAdd(&g_prep_done, 1u);
            while (ld_acquire_u32(&g_prep_done) < (unsigned)NPREP) __nanosleep(200);
        }
        __syncthreads();

        // ---------------- ball branch (warp per query, pipelined vs FPS) ----------------
        const int wid  = threadIdx.x >> 5;
        const int lane = threadIdx.x & 31;
        int* bufw = (int*)sm + wid * 32;
        const int gw = (blockIdx.x - BATCH) * 32 + wid;

        for (int q = gw; q < BATCH * M_PTS; q += NPREP * 32) {
            const int b = q & 7;
            const int m = q >> 3;

            // wait for centroid m of batch b (all lanes: one coalesced poll)
            unsigned p;
            do {
                p = ld_acquire_u32(&g_fps_progress[b]);
                if (p <= (unsigned)m) __nanosleep(200);
            } while (p <= (unsigned)m);

            const float cx = g_center[b][m][0];
            const float cy = g_center[b][m][1];
            const float cz = g_center[b][m][2];
            const float* __restrict__ px = g_xyzT[b][0];
            const float* __restrict__ py = g_xyzT[b][1];
            const float* __restrict__ pz = g_xyzT[b][2];

            int count = 0;
            for (int n0 = 0; n0 < N_PTS; n0 += 32) {
                int i = n0 + lane;
                float dx = px[i] - cx;
                float dy = py[i] - cy;
                float dz = pz[i] - cz;
                float d  = sqdist(dx, dy, dz);
                bool pr  = (d <= 0.16f);
                unsigned mask = __ballot_sync(0xffffffffu, pr);
                int pos = count + __popc(mask & ((1u << lane) - 1u));
                if (pr && pos < 32) bufw[pos] = i;
                count += __popc(mask);
                if (count >= 32) break;
            }
            __syncwarp();
            int first = bufw[0];
            int v = (lane < count) ? bufw[lane] : first;
            g_ball[b][m][lane] = v;
            __syncwarp();
        }
        return;
    }

    // ---------------- FPS branch (R7 — known good + progress publish) ----------------
    float* sx = sm;
    float* sy = sm + N_PTS;
    float* zp = sm + 2 * N_PTS;
    unsigned* rv = (unsigned*)(sm + 3 * N_PTS);   // [2][32]
    unsigned* ri = rv + 64;                        // [2][32]

    const int b    = blockIdx.x;
    const int tid  = threadIdx.x;
    const int lane = tid & 31;
    const int wid  = tid >> 5;

    const float* gx = xyz + b * N_PTS * 3;
    for (int t = tid; t < N_PTS; t += 1024) {
        float x = gx[3 * t + 0];
        float y = gx[3 * t + 1];
        float z = gx[3 * t + 2];
        sx[t] = x;
        sy[t] = y;
        int k = t >> 10, tt = t & 1023;
        zp[(((k >> 1) * 1024) + tt) * 2 + (k & 1)] = z;
    }
    __syncthreads();

    unsigned long long xx2[8], yy2[8];
    float dist[16];
#pragma unroll
    for (int j = 0; j < 8; ++j) {
        xx2[j] = pk2(sx[(2 * j) * 1024 + tid], sx[(2 * j + 1) * 1024 + tid]);
        yy2[j] = pk2(sy[(2 * j) * 1024 + tid], sy[(2 * j + 1) * 1024 + tid]);
    }
#pragma unroll
    for (int k = 0; k < 16; ++k) dist[k] = 1e10f;

    float cx = sx[0], cy = sy[0], cz = zp[0];
    int   cidx = 0;

    const unsigned long long* zp64 = (const unsigned long long*)zp;

    for (int it = 0; it < M_PTS; ++it) {
        if (tid == 0) {
            out[OUT_XYZ_OFF + (b * M_PTS + it) * 3 + 0] = cx;
            out[OUT_XYZ_OFF + (b * M_PTS + it) * 3 + 1] = cy;
            out[OUT_XYZ_OFF + (b * M_PTS + it) * 3 + 2] = cz;
            out[OUT_IDX_OFF + b * M_PTS + it] = (float)cidx;
            g_center[b][it][0] = cx;
            g_center[b][it][1] = cy;
            g_center[b][it][2] = cz;
            st_release_u32(&g_fps_progress[b], (unsigned)(it + 1));
        }
        if (it == M_PTS - 1) break;

        const unsigned long long ncx = pk2(-cx, -cx);
        const unsigned long long ncy = pk2(-cy, -cy);
        const unsigned long long ncz = pk2(-cz, -cz);

        float mx = -1.0f;
#pragma unroll
        for (int j = 0; j < 8; ++j) {
            unsigned long long zz = zp64[j * 1024 + tid];
            unsigned long long dx = add2(xx2[j], ncx);
            unsigned long long dy = add2(yy2[j], ncy);
            unsigned long long dz = add2(zz,     ncz);
            unsigned long long s  = add2(add2(mul2(dx, dx), mul2(dy, dy)), mul2(dz, dz));
            float d0, d1;
            upk2(s, d0, d1);
            float n0 = fminf(dist[2 * j + 0], d0);
            float n1 = fminf(dist[2 * j + 1], d1);
            dist[2 * j + 0] = n0;
            dist[2 * j + 1] = n1;
            mx = fmaxf(mx, fmaxf(n0, n1));
        }

        int bk = 0;
#pragma unroll
        for (int k = 15; k >= 0; --k)
            if (dist[k] == mx) bk = k;

        const int par = (it & 1) * 32;
        unsigned mxb  = __float_as_uint(mx);
        unsigned wmax = __reduce_max_sync(0xffffffffu, mxb);
        unsigned cand = (mxb == wmax) ? (unsigned)(bk * 1024 + tid) : 0xffffffffu;
        unsigned wi   = __reduce_min_sync(0xffffffffu, cand);
        if (lane == 0) { rv[par + wid] = wmax; ri[par + wid] = wi; }
        __syncthreads();

        unsigned v    = rv[par + lane];
        unsigned i    = ri[par + lane];
        unsigned bmax = __reduce_max_sync(0xffffffffu, v);
        unsigned c2   = (v == bmax) ? i : 0xffffffffu;
        unsigned gi   = __reduce_min_sync(0xffffffffu, c2);
        {
            int p = (int)gi;
            int k = p >> 10, tt = p & 1023;
            cx = sx[p];
            cy = sy[p];
            cz = zp[(((k >> 1) * 1024) + tt) * 2 + (k & 1)];
            cidx = p;
        }
    }
}

// ======================= fused MLP + maxpool (all-tf32 mma) =======================
#define STR 72
#define WPAD 264
#define W0STR 72
#define OFF_XS  0
#define OFF_H1  (OFF_XS + 72 * STR)      // 5184
#define OFF_H2  (OFF_H1 + 64 * STR)      // 9792
#define OFF_WS  (OFF_H2 + 128 * STR)     // 19008
#define OFF_SIDX (OFF_WS + 32 * WPAD)    // 27456
#define OFF_SCTR (OFF_SIDX + 64)
#define MLP_SMEM_FLOATS (OFF_SCTR + 8)   // 27528 floats = 110.1 KB

__device__ __forceinline__ void mlp_layer1_mma(
    const float* __restrict__ bias,
    const float* __restrict__ scale,
    const float* __restrict__ shift,
    const float* X, float* H1, float* Ws)
{
    const int tid   = threadIdx.x;
    const int wid   = tid >> 5;
    const int lane  = tid & 31;
    const int qid   = lane >> 2;
    const int qlane = lane & 3;
    const int mw    = wid & 3;
    const int nh    = wid >> 2;

    for (int e = tid; e < 72 * 64; e += 256) {
        int k = e >> 6, o = e & 63;
        Ws[k * W0STR + o] = g_Wt0[e];
    }
    __syncthreads();

    float acc[4][4];
#pragma unroll
    for (int nt = 0; nt < 4; ++nt)
#pragma unroll
        for (int c = 0; c < 4; ++c) acc[nt][c] = 0.0f;

#pragma unroll
    for (int ks = 0; ks < 9; ++ks) {
        const int kb = ks * 8 + qlane;
        uint32_t bfr[4][2];
        const float* x0 = X + kb * STR;
        const float* x1 = X + (kb + 4) * STR;
#pragma unroll
        for (int nt = 0; nt < 4; ++nt) {
            int n = nh * 32 + nt * 8 + qid;
            bfr[nt][0] = __float_as_uint(x0[n]);
            bfr[nt][1] = __float_as_uint(x1[n]);
        }
        uint32_t afr[4];
        const float* w0 = Ws + kb * W0STR;
        const float* w1 = Ws + (kb + 4) * W0STR;
        int m = mw * 16 + qid;
        afr[0] = __float_as_uint(w0[m]);
        afr[1] = __float_as_uint(w0[m + 8]);
        afr[2] = __float_as_uint(w1[m]);
        afr[3] = __float_as_uint(w1[m + 8]);
#pragma unroll
        for (int nt = 0; nt < 4; ++nt)
            mma_tf32(acc[nt], afr, bfr[nt]);
    }
    __syncthreads();

#pragma unroll
    for (int dr = 0; dr < 2; ++dr) {
        int o = mw * 16 + qid + dr * 8;
        float bb = bias[o], ss = scale[o], tt = shift[o];
#pragma unroll
        for (int nt = 0; nt < 4; ++nt) {
            float v0 = fmaxf((acc[nt][dr * 2 + 0] + bb) * ss + tt, 0.0f);
            float v1 = fmaxf((acc[nt][dr * 2 + 1] + bb) * ss + tt, 0.0f);
            int n = nh * 32 + nt * 8 + qlane * 2;
            H1[o * STR + n + 0] = to_tf32(v0);
            H1[o * STR + n + 1] = to_tf32(v1);
        }
    }
}

__device__ __forceinline__ void mlp_layer2_mma(
    const float* __restrict__ bias,
    const float* __restrict__ scale,
    const float* __restrict__ shift,
    const float* H1, float* H2, float* Ws)
{
    const int tid   = threadIdx.x;
    const int wid   = tid >> 5;
    const int lane  = tid & 31;
    const int qid   = lane >> 2;
    const int qlane = lane & 3;

    float acc[8][4];
#pragma unroll
    for (int nt = 0; nt < 8; ++nt)
#pragma unroll
        for (int c = 0; c < 4; ++c) acc[nt][c] = 0.0f;

    for (int kc = 0; kc < 64; kc += 32) {
        __syncthreads();
        for (int e = tid; e < 32 * 128; e += 256) {
            int k = e >> 7, o = e & 127;
            Ws[k * WPAD + o] = g_Wt1[(kc + k) * 128 + o];
        }
        __syncthreads();
#pragma unroll
        for (int ks = 0; ks < 4; ++ks) {
            const int kb = ks * 8 + qlane;
            uint32_t bfr[8][2];
            const float* h0 = H1 + (kc + kb) * STR;
            const float* h1 = H1 + (kc + kb + 4) * STR;
#pragma unroll
            for (int nt = 0; nt < 8; ++nt) {
                int n = nt * 8 + qid;
                bfr[nt][0] = __float_as_uint(h0[n]);
                bfr[nt][1] = __float_as_uint(h1[n]);
            }
            uint32_t afr[4];
            const float* w0 = Ws + kb * WPAD;
            const float* w1 = Ws + (kb + 4) * WPAD;
            int m = wid * 16 + qid;
            afr[0] = __float_as_uint(w0[m]);
            afr[1] = __float_as_uint(w0[m + 8]);
            afr[2] = __float_as_uint(w1[m]);
            afr[3] = __float_as_uint(w1[m + 8]);
#pragma unroll
            for (int nt = 0; nt < 8; ++nt)
                mma_tf32(acc[nt], afr, bfr[nt]);
        }
    }
    __syncthreads();

#pragma unroll
    for (int dr = 0; dr < 2; ++dr) {
        int o = wid * 16 + qid + dr * 8;
        float bb = bias[o], ss = scale[o], tt = shift[o];
#pragma unroll
        for (int nt = 0; nt < 8; ++nt) {
            float v0 = fmaxf((acc[nt][dr * 2 + 0] + bb) * ss + tt, 0.0f);
            float v1 = fmaxf((acc[nt][dr * 2 + 1] + bb) * ss + tt, 0.0f);
            H2[o * STR + nt * 8 + qlane * 2 + 0] = to_tf32(v0);
            H2[o * STR + nt * 8 + qlane * 2 + 1] = to_tf32(v1);
        }
    }
}

__device__ __forceinline__ void mlp_layer3_mma(
    const float* __restrict__ bias,
    const float* __restrict__ scale,
    const float* __restrict__ shift,
    const float* H2, float* Ws,
    float* __restrict__ outF, int b, int m0)
{
    const int tid   = threadIdx.x;
    const int wid   = tid >> 5;
    const int lane  = tid & 31;
    const int qid   = lane >> 2;
    const int qlane = lane & 3;

    float acc[2][8][4];
#pragma unroll
    for (int mt = 0; mt < 2; ++mt)
#pragma unroll
        for (int nt = 0; nt < 8; ++nt)
#pragma unroll
            for (int c = 0; c < 4; ++c) acc[mt][nt][c] = 0.0f;

    for (int kc = 0; kc < 128; kc += 32) {
        __syncthreads();
        for (int e = tid; e < 32 * 256; e += 256) {
            int k = e >> 8, o = e & 255;
            Ws[k * WPAD + o] = g_Wt2[(kc + k) * 256 + o];
        }
        __syncthreads();
#pragma unroll
        for (int ks = 0; ks < 4; ++ks) {
            const int kb = ks * 8 + qlane;
            uint32_t bfr[8][2];
            const float* h0 = H2 + (kc + kb) * STR;
            const float* h1 = H2 + (kc + kb + 4) * STR;
#pragma unroll
            for (int nt = 0; nt < 8; ++nt) {
                int n = nt * 8 + qid;
                bfr[nt][0] = __float_as_uint(h0[n]);
                bfr[nt][1] = __float_as_uint(h1[n]);
            }
            uint32_t afr[2][4];
            const float* w0 = Ws + kb * WPAD;
            const float* w1 = Ws + (kb + 4) * WPAD;
#pragma unroll
            for (int mt = 0; mt < 2; ++mt) {
                int m = wid * 32 + mt * 16 + qid;
                afr[mt][0] = __float_as_uint(w0[m]);
                afr[mt][1] = __float_as_uint(w0[m + 8]);
                afr[mt][2] = __float_as_uint(w1[m]);
                afr[mt][3] = __float_as_uint(w1[m + 8]);
            }
#pragma unroll
            for (int mt = 0; mt < 2; ++mt)
#pragma unroll
                for (int nt = 0; nt < 8; ++nt)
                    mma_tf32(acc[mt][nt], afr[mt], bfr[nt]);
        }
    }

#pragma unroll
    for (int mt = 0; mt < 2; ++mt) {
#pragma unroll
        for (int dr = 0; dr < 2; ++dr) {
            int o = wid * 32 + mt * 16 + qid + dr * 8;
            float bb = bias[o], ss = scale[o], tt = shift[o];
            float vA = 0.0f, vB = 0.0f;
#pragma unroll
            for (int nt = 0; nt < 8; ++nt) {
                float v0 = fmaxf((acc[mt][nt][dr * 2 + 0] + bb) * ss + tt, 0.0f);
                float v1 = fmaxf((acc[mt][nt][dr * 2 + 1] + bb) * ss + tt, 0.0f);
                float v  = fmaxf(v0, v1);
                if (nt < 4) vA = fmaxf(vA, v); else vB = fmaxf(vB, v);
            }
            vA = fmaxf(vA, __shfl_xor_sync(0xffffffffu, vA, 1));
            vA = fmaxf(vA, __shfl_xor_sync(0xffffffffu, vA, 2));
            vB = fmaxf(vB, __shfl_xor_sync(0xffffffffu, vB, 1));
            vB = fmaxf(vB, __shfl_xor_sync(0xffffffffu, vB, 2));
            if (qlane == 0) {
                outF[(b * 256 + o) * M_PTS + m0]     = vA;
                outF[(b * 256 + o) * M_PTS + m0 + 1] = vB;
            }
        }
    }
}

__global__ __launch_bounds__(256, 2) void mlp_kernel(
    const float* __restrict__ b0, const float* __restrict__ s0, const float* __restrict__ t0,
    const float* __restrict__ b1, const float* __restrict__ s1, const float* __restrict__ t1,
    const float* __restrict__ b2, const float* __restrict__ s2, const float* __restrict__ t2,
    float* __restrict__ outF)
{
    extern __shared__ float sm[];
    const int tid = threadIdx.x;
    const int b   = blockIdx.y;
    const int m0  = blockIdx.x * 2;

    int*   sIdx = (int*)(sm + OFF_SIDX);
    float* sCtr = sm + OFF_SCTR;

    if (tid < 64) sIdx[tid] = g_ball[b][m0 + (tid >> 5)][tid & 31];
    if (tid < 6)  sCtr[tid] = g_center[b][m0 + tid / 3][tid % 3];
    __syncthreads();

    {
        int col  = tid >> 2;
        int part = tid & 3;
        int p    = sIdx[col];
        int half = col >> 5;
        float cx = sCtr[half * 3 + 0];
        float cy = sCtr[half * 3 + 1];
        float cz = sCtr[half * 3 + 2];
        const float* fp = &g_featT[b][p][0];
#pragma unroll
        for (int jj = 0; jj < 18; ++jj) {
            int r = part * 18 + jj;
            float v;
            if (r == 0)      v = to_tf32(g_xyzT[b][0][p] - cx);
            else if (r == 1) v = to_tf32(g_xyzT[b][1][p] - cy);
            else if (r == 2) v = to_tf32(g_xyzT[b][2][p] - cz);
            else if (r < 67) v = to_tf32(fp[r - 3]);
            else             v = 0.0f;
            sm[OFF_XS + r * STR + col] = v;
        }
    }
    __syncthreads();

    mlp_layer1_mma(b0, s0, t0, sm + OFF_XS, sm + OFF_H1, sm + OFF_WS);
    mlp_layer2_mma(b1, s1, t1, sm + OFF_H1, sm + OFF_H2, sm + OFF_WS);
    mlp_layer3_mma(b2, s2, t2, sm + OFF_H2, sm + OFF_WS, outF, b, m0);
}

// ======================= launch =======================
extern "C" void kernel_launch(void* const* d_in, const int* in_sizes, int n_in,
                              void* d_out, int out_size) {
    const float* xyz  = (const float*)d_in[0];
    const float* feat = (const float*)d_in[1];
    const float* W0 = (const float*)d_in[2];
    const float* b0 = (const float*)d_in[3];
    const float* s0 = (const float*)d_in[4];
    const float* t0 = (const float*)d_in[5];
    const float* W1 = (const float*)d_in[6];
    const float* b1 = (const float*)d_in[7];
    const float* s1 = (const float*)d_in[8];
    const float* t1 = (const float*)d_in[9];
    const float* W2 = (const float*)d_in[10];
    const float* b2 = (const float*)d_in[11];
    const float* s2 = (const float*)d_in[12];
    const float* t2 = (const float*)d_in[13];
    float* out = (float*)d_out;

    const int fps_smem = (3 * N_PTS + 128) * sizeof(float);
    const int mlp_smem = MLP_SMEM_FLOATS * sizeof(float);
    cudaFuncSetAttribute(fps_prep_kernel, cudaFuncAttributeMaxDynamicSharedMemorySize, fps_smem);
    cudaFuncSetAttribute(mlp_kernel, cudaFuncAttributeMaxDynamicSharedMemorySize, mlp_smem);

    reset_kernel<<<1, 32>>>();
    fps_prep_kernel<<<BATCH + NPREP, 1024, fps_smem>>>(xyz, feat, W0, W1, W2, out);
    mlp_kernel<<<dim3(M_PTS / 2, BATCH), 256, mlp_smem>>>(
        b0, s0, t0, b1, s1, t1, b2, s2, t2, out + OUT_FEAT_OFF);
}

// round 14
// speedup vs baseline: 1.3953x; 1.3953x over previous
#include <cuda_runtime.h>
#include <cstdint>

#define BATCH 8
#define N_PTS 16384
#define M_PTS 1024
#define KS    32
#define CFEAT 64

#define NPREP 140     // prep/ball CTAs in the fused launch

// ---- output layout (float32): [new_xyz | new_features | indices] ----
#define OUT_XYZ_OFF  0
#define OUT_FEAT_OFF (BATCH * M_PTS * 3)                       // 24576
#define OUT_IDX_OFF  (OUT_FEAT_OFF + BATCH * 256 * M_PTS)      // 2121728

// ---- device scratch ----
__device__ float g_xyzT[BATCH][3][N_PTS];
__device__ float g_featT[BATCH][N_PTS][CFEAT];
__device__ float g_Wt0[72 * 64];            // tf32-rounded at prep
__device__ float g_Wt1[64 * 128];           // tf32-rounded at prep
__device__ float g_Wt2[128 * 256];          // tf32-rounded at prep
__device__ int   g_ball[BATCH][M_PTS][KS];
__device__ float g_center[BATCH][M_PTS][3];

// producer->consumer state (reset every launch)
__device__ unsigned g_fps_progress[BATCH];
__device__ unsigned g_prep_done;

// exact (non-FMA) squared distance, left-to-right sum — must match XLA
__device__ __forceinline__ float sqdist(float dx, float dy, float dz) {
    float d = __fmul_rn(dx, dx);
    d = __fadd_rn(d, __fmul_rn(dy, dy));
    d = __fadd_rn(d, __fmul_rn(dz, dz));
    return d;
}

// ---- packed f32x2 helpers ----
__device__ __forceinline__ unsigned long long pk2(float a, float b) {
    unsigned long long r;
    asm("mov.b64 %0, {%1, %2};" : "=l"(r) : "f"(a), "f"(b));
    return r;
}
__device__ __forceinline__ void upk2(unsigned long long v, float& a, float& b) {
    asm("mov.b64 {%0, %1}, %2;" : "=f"(a), "=f"(b) : "l"(v));
}
__device__ __forceinline__ unsigned long long add2(unsigned long long a, unsigned long long b) {
    unsigned long long r;
    asm("add.rn.f32x2 %0, %1, %2;" : "=l"(r) : "l"(a), "l"(b));
    return r;
}
__device__ __forceinline__ unsigned long long mul2(unsigned long long a, unsigned long long b) {
    unsigned long long r;
    asm("mul.rn.f32x2 %0, %1, %2;" : "=l"(r) : "l"(a), "l"(b));
    return r;
}

// ---- tf32 helpers ----
__device__ __forceinline__ float to_tf32(float x) {
    uint32_t u;
    asm("cvt.rna.tf32.f32 %0, %1;" : "=r"(u) : "f"(x));
    return __uint_as_float(u);
}
__device__ __forceinline__ void mma_tf32(float* d, const uint32_t* a, const uint32_t* b) {
    asm volatile(
        "mma.sync.aligned.m16n8k8.row.col.f32.tf32.tf32.f32 "
        "{%0,%1,%2,%3}, {%4,%5,%6,%7}, {%8,%9}, {%0,%1,%2,%3};"
        : "+f"(d[0]), "+f"(d[1]), "+f"(d[2]), "+f"(d[3])
        : "r"(a[0]), "r"(a[1]), "r"(a[2]), "r"(a[3]), "r"(b[0]), "r"(b[1]));
}

// ---- release/acquire ----
__device__ __forceinline__ void st_release_u32(unsigned* p, unsigned v) {
    asm volatile("st.release.gpu.global.u32 [%0], %1;" :: "l"(p), "r"(v) : "memory");
}
__device__ __forceinline__ unsigned ld_acquire_u32(const unsigned* p) {
    unsigned v;
    asm volatile("ld.acquire.gpu.global.u32 %0, [%1];" : "=r"(v) : "l"(p) : "memory");
    return v;
}

// ======================= reset (graph-replay safety) =======================
__global__ void reset_kernel() {
    if (threadIdx.x < BATCH) g_fps_progress[threadIdx.x] = 0u;
    if (threadIdx.x == BATCH) g_prep_done = 0u;
}

// ======================= fused FPS + prep + ball =======================
// CTAs 0..7: FPS (publishes per-iteration progress, one release store/iter).
// CTAs 8..147: prep, then ball. Warp0 = sole L2 poller (mirrors progress into
// smem); warps 1..31 consume via smem spin + single confirming acquire.
__global__ __launch_bounds__(1024, 1) void fps_prep_kernel(
    const float* __restrict__ xyz, const float* __restrict__ feat,
    const float* __restrict__ W0, const float* __restrict__ W1,
    const float* __restrict__ W2, float* __restrict__ out)
{
    extern __shared__ float sm[];

    if (blockIdx.x >= BATCH) {
        // ---------------- prep branch ----------------
        const int gtid   = (blockIdx.x - BATCH) * 1024 + threadIdx.x;
        const int stride = NPREP * 1024;

        for (int id = gtid; id < 72 * 64 + 64 * 128 + 128 * 256; id += stride) {
            if (id < 72 * 64) {
                int c = id >> 6, o = id & 63;
                g_Wt0[id] = (c < 67) ? to_tf32(W0[o * 67 + c]) : 0.0f;
            } else if (id < 72 * 64 + 64 * 128) {
                int e = id - 72 * 64;
                int c = e >> 7, o = e & 127;
                g_Wt1[e] = to_tf32(W1[o * 64 + c]);
            } else {
                int e = id - 72 * 64 - 64 * 128;
                int c = e >> 8, o = e & 255;
                g_Wt2[e] = to_tf32(W2[o * 128 + c]);
            }
        }
        for (int id = gtid; id < BATCH * 3 * N_PTS; id += stride) {
            int b = id / (3 * N_PTS);
            int r = id % (3 * N_PTS);
            int c = r / N_PTS;
            int n = r % N_PTS;
            g_xyzT[b][c][n] = xyz[(b * N_PTS + n) * 3 + c];
        }
        const float4* f4 = (const float4*)feat;
        for (int id = gtid; id < (BATCH * CFEAT * N_PTS) / 4; id += stride) {
            float4 v = f4[id];
            int lin = id * 4;
            int b = lin >> 20;
            int r = lin & 0xFFFFF;
            int c = r >> 14;
            int n = r & 16383;
            g_featT[b][n + 0][c] = v.x;
            g_featT[b][n + 1][c] = v.y;
            g_featT[b][n + 2][c] = v.z;
            g_featT[b][n + 3][c] = v.w;
        }

        // signal prep complete; wait for all prep CTAs (xyzT must be full)
        __syncthreads();
        if (threadIdx.x == 0) {
            __threadfence();
            atomicAdd(&g_prep_done, 1u);
            while (ld_acquire_u32(&g_prep_done) < (unsigned)NPREP) __nanosleep(200);
        }
        __syncthreads();

        // ---------------- ball branch ----------------
        const int wid  = threadIdx.x >> 5;
        const int lane = threadIdx.x & 31;
        int* bufs = (int*)sm;                                   // [32][32]
        volatile unsigned* s_prog = (volatile unsigned*)(bufs + 32 * 32);

        if (wid == 0) {
            if (lane < BATCH) s_prog[lane] = 0u;
            __syncwarp();
            // sole L2 poller for this CTA
            for (;;) {
                unsigned p = (lane < BATCH) ? ld_acquire_u32(&g_fps_progress[lane]) : M_PTS;
                if (lane < BATCH) s_prog[lane] = p;
                unsigned donemask = __ballot_sync(0xffffffffu, p >= (unsigned)M_PTS);
                if (donemask == 0xffffffffu) break;
                __nanosleep(1000);
            }
            return;
        }
        // worker warps need s_prog initialized — cheap local wait (poller
        // writes it within a few cycles of the CTA-wide syncthreads above)
        // s_prog starts undefined; spin below handles it only after first write.
        // To be safe, wait until poller's first publish: s_prog values are
        // either 0.. or garbage; force ordering with a block barrier:
        // (all 32 warps reach here post-__syncthreads above; poller inits then
        //  enters loop — add one more syncthreads is impossible (poller loops).
        //  Instead workers poll the GLOBAL flag ONCE first to bound garbage.)
        const int worker = (blockIdx.x - BATCH) * 31 + (wid - 1);
        int* bufw = bufs + wid * 32;

        for (int q = worker; q < BATCH * M_PTS; q += NPREP * 31) {
            const int b = q & 7;
            const int m = q >> 3;

            // cheap smem spin (value is monotonic; garbage handled by confirm)
            for (;;) {
                unsigned p = s_prog[b];
                if (p > (unsigned)m && p <= (unsigned)M_PTS) {
                    // confirm + establish release-acquire chain to g_center
                    if (ld_acquire_u32(&g_fps_progress[b]) > (unsigned)m) break;
                }
                __nanosleep(400);
            }

            const float cx = g_center[b][m][0];
            const float cy = g_center[b][m][1];
            const float cz = g_center[b][m][2];
            const float* __restrict__ px = g_xyzT[b][0];
            const float* __restrict__ py = g_xyzT[b][1];
            const float* __restrict__ pz = g_xyzT[b][2];

            int count = 0;
            for (int n0 = 0; n0 < N_PTS; n0 += 32) {
                int i = n0 + lane;
                float dx = px[i] - cx;
                float dy = py[i] - cy;
                float dz = pz[i] - cz;
                float d  = sqdist(dx, dy, dz);
                bool pr  = (d <= 0.16f);
                unsigned mask = __ballot_sync(0xffffffffu, pr);
                int pos = count + __popc(mask & ((1u << lane) - 1u));
                if (pr && pos < 32) bufw[pos] = i;
                count += __popc(mask);
                if (count >= 32) break;
            }
            __syncwarp();
            int first = bufw[0];
            int v = (lane < count) ? bufw[lane] : first;
            g_ball[b][m][lane] = v;
            __syncwarp();
        }
        return;
    }

    // ---------------- FPS branch (R7 — known good + progress publish) ----------------
    float* sx = sm;
    float* sy = sm + N_PTS;
    float* zp = sm + 2 * N_PTS;
    unsigned* rv = (unsigned*)(sm + 3 * N_PTS);   // [2][32]
    unsigned* ri = rv + 64;                        // [2][32]

    const int b    = blockIdx.x;
    const int tid  = threadIdx.x;
    const int lane = tid & 31;
    const int wid  = tid >> 5;

    const float* gx = xyz + b * N_PTS * 3;
    for (int t = tid; t < N_PTS; t += 1024) {
        float x = gx[3 * t + 0];
        float y = gx[3 * t + 1];
        float z = gx[3 * t + 2];
        sx[t] = x;
        sy[t] = y;
        int k = t >> 10, tt = t & 1023;
        zp[(((k >> 1) * 1024) + tt) * 2 + (k & 1)] = z;
    }
    __syncthreads();

    unsigned long long xx2[8], yy2[8];
    float dist[16];
#pragma unroll
    for (int j = 0; j < 8; ++j) {
        xx2[j] = pk2(sx[(2 * j) * 1024 + tid], sx[(2 * j + 1) * 1024 + tid]);
        yy2[j] = pk2(sy[(2 * j) * 1024 + tid], sy[(2 * j + 1) * 1024 + tid]);
    }
#pragma unroll
    for (int k = 0; k < 16; ++k) dist[k] = 1e10f;

    float cx = sx[0], cy = sy[0], cz = zp[0];
    int   cidx = 0;

    const unsigned long long* zp64 = (const unsigned long long*)zp;

    for (int it = 0; it < M_PTS; ++it) {
        if (tid == 0) {
            out[OUT_XYZ_OFF + (b * M_PTS + it) * 3 + 0] = cx;
            out[OUT_XYZ_OFF + (b * M_PTS + it) * 3 + 1] = cy;
            out[OUT_XYZ_OFF + (b * M_PTS + it) * 3 + 2] = cz;
            out[OUT_IDX_OFF + b * M_PTS + it] = (float)cidx;
            g_center[b][it][0] = cx;
            g_center[b][it][1] = cy;
            g_center[b][it][2] = cz;
            st_release_u32(&g_fps_progress[b], (unsigned)(it + 1));
        }
        if (it == M_PTS - 1) break;

        const unsigned long long ncx = pk2(-cx, -cx);
        const unsigned long long ncy = pk2(-cy, -cy);
        const unsigned long long ncz = pk2(-cz, -cz);

        float mx = -1.0f;
#pragma unroll
        for (int j = 0; j < 8; ++j) {
            unsigned long long zz = zp64[j * 1024 + tid];
            unsigned long long dx = add2(xx2[j], ncx);
            unsigned long long dy = add2(yy2[j], ncy);
            unsigned long long dz = add2(zz,     ncz);
            unsigned long long s  = add2(add2(mul2(dx, dx), mul2(dy, dy)), mul2(dz, dz));
            float d0, d1;
            upk2(s, d0, d1);
            float n0 = fminf(dist[2 * j + 0], d0);
            float n1 = fminf(dist[2 * j + 1], d1);
            dist[2 * j + 0] = n0;
            dist[2 * j + 1] = n1;
            mx = fmaxf(mx, fmaxf(n0, n1));
        }

        int bk = 0;
#pragma unroll
        for (int k = 15; k >= 0; --k)
            if (dist[k] == mx) bk = k;

        const int par = (it & 1) * 32;
        unsigned mxb  = __float_as_uint(mx);
        unsigned wmax = __reduce_max_sync(0xffffffffu, mxb);
        unsigned cand = (mxb == wmax) ? (unsigned)(bk * 1024 + tid) : 0xffffffffu;
        unsigned wi   = __reduce_min_sync(0xffffffffu, cand);
        if (lane == 0) { rv[par + wid] = wmax; ri[par + wid] = wi; }
        __syncthreads();

        unsigned v    = rv[par + lane];
        unsigned i    = ri[par + lane];
        unsigned bmax = __reduce_max_sync(0xffffffffu, v);
        unsigned c2   = (v == bmax) ? i : 0xffffffffu;
        unsigned gi   = __reduce_min_sync(0xffffffffu, c2);
        {
            int p = (int)gi;
            int k = p >> 10, tt = p & 1023;
            cx = sx[p];
            cy = sy[p];
            cz = zp[(((k >> 1) * 1024) + tt) * 2 + (k & 1)];
            cidx = p;
        }
    }
}

// ======================= fused MLP + maxpool (all-tf32 mma) =======================
#define STR 72
#define WPAD 264
#define W0STR 72
#define OFF_XS  0
#define OFF_H1  (OFF_XS + 72 * STR)      // 5184
#define OFF_H2  (OFF_H1 + 64 * STR)      // 9792
#define OFF_WS  (OFF_H2 + 128 * STR)     // 19008
#define OFF_SIDX (OFF_WS + 32 * WPAD)    // 27456
#define OFF_SCTR (OFF_SIDX + 64)
#define MLP_SMEM_FLOATS (OFF_SCTR + 8)   // 27528 floats = 110.1 KB

__device__ __forceinline__ void mlp_layer1_mma(
    const float* __restrict__ bias,
    const float* __restrict__ scale,
    const float* __restrict__ shift,
    const float* X, float* H1, float* Ws)
{
    const int tid   = threadIdx.x;
    const int wid   = tid >> 5;
    const int lane  = tid & 31;
    const int qid   = lane >> 2;
    const int qlane = lane & 3;
    const int mw    = wid & 3;
    const int nh    = wid >> 2;

    for (int e = tid; e < 72 * 64; e += 256) {
        int k = e >> 6, o = e & 63;
        Ws[k * W0STR + o] = g_Wt0[e];
    }
    __syncthreads();

    float acc[4][4];
#pragma unroll
    for (int nt = 0; nt < 4; ++nt)
#pragma unroll
        for (int c = 0; c < 4; ++c) acc[nt][c] = 0.0f;

#pragma unroll
    for (int ks = 0; ks < 9; ++ks) {
        const int kb = ks * 8 + qlane;
        uint32_t bfr[4][2];
        const float* x0 = X + kb * STR;
        const float* x1 = X + (kb + 4) * STR;
#pragma unroll
        for (int nt = 0; nt < 4; ++nt) {
            int n = nh * 32 + nt * 8 + qid;
            bfr[nt][0] = __float_as_uint(x0[n]);
            bfr[nt][1] = __float_as_uint(x1[n]);
        }
        uint32_t afr[4];
        const float* w0 = Ws + kb * W0STR;
        const float* w1 = Ws + (kb + 4) * W0STR;
        int m = mw * 16 + qid;
        afr[0] = __float_as_uint(w0[m]);
        afr[1] = __float_as_uint(w0[m + 8]);
        afr[2] = __float_as_uint(w1[m]);
        afr[3] = __float_as_uint(w1[m + 8]);
#pragma unroll
        for (int nt = 0; nt < 4; ++nt)
            mma_tf32(acc[nt], afr, bfr[nt]);
    }
    __syncthreads();

#pragma unroll
    for (int dr = 0; dr < 2; ++dr) {
        int o = mw * 16 + qid + dr * 8;
        float bb = bias[o], ss = scale[o], tt = shift[o];
#pragma unroll
        for (int nt = 0; nt < 4; ++nt) {
            float v0 = fmaxf((acc[nt][dr * 2 + 0] + bb) * ss + tt, 0.0f);
            float v1 = fmaxf((acc[nt][dr * 2 + 1] + bb) * ss + tt, 0.0f);
            int n = nh * 32 + nt * 8 + qlane * 2;
            H1[o * STR + n + 0] = to_tf32(v0);
            H1[o * STR + n + 1] = to_tf32(v1);
        }
    }
}

__device__ __forceinline__ void mlp_layer2_mma(
    const float* __restrict__ bias,
    const float* __restrict__ scale,
    const float* __restrict__ shift,
    const float* H1, float* H2, float* Ws)
{
    const int tid   = threadIdx.x;
    const int wid   = tid >> 5;
    const int lane  = tid & 31;
    const int qid   = lane >> 2;
    const int qlane = lane & 3;

    float acc[8][4];
#pragma unroll
    for (int nt = 0; nt < 8; ++nt)
#pragma unroll
        for (int c = 0; c < 4; ++c) acc[nt][c] = 0.0f;

    for (int kc = 0; kc < 64; kc += 32) {
        __syncthreads();
        for (int e = tid; e < 32 * 128; e += 256) {
            int k = e >> 7, o = e & 127;
            Ws[k * WPAD + o] = g_Wt1[(kc + k) * 128 + o];
        }
        __syncthreads();
#pragma unroll
        for (int ks = 0; ks < 4; ++ks) {
            const int kb = ks * 8 + qlane;
            uint32_t bfr[8][2];
            const float* h0 = H1 + (kc + kb) * STR;
            const float* h1 = H1 + (kc + kb + 4) * STR;
#pragma unroll
            for (int nt = 0; nt < 8; ++nt) {
                int n = nt * 8 + qid;
                bfr[nt][0] = __float_as_uint(h0[n]);
                bfr[nt][1] = __float_as_uint(h1[n]);
            }
            uint32_t afr[4];
            const float* w0 = Ws + kb * WPAD;
            const float* w1 = Ws + (kb + 4) * WPAD;
            int m = wid * 16 + qid;
            afr[0] = __float_as_uint(w0[m]);
            afr[1] = __float_as_uint(w0[m + 8]);
            afr[2] = __float_as_uint(w1[m]);
            afr[3] = __float_as_uint(w1[m + 8]);
#pragma unroll
            for (int nt = 0; nt < 8; ++nt)
                mma_tf32(acc[nt], afr, bfr[nt]);
        }
    }
    __syncthreads();

#pragma unroll
    for (int dr = 0; dr < 2; ++dr) {
        int o = wid * 16 + qid + dr * 8;
        float bb = bias[o], ss = scale[o], tt = shift[o];
#pragma unroll
        for (int nt = 0; nt < 8; ++nt) {
            float v0 = fmaxf((acc[nt][dr * 2 + 0] + bb) * ss + tt, 0.0f);
            float v1 = fmaxf((acc[nt][dr * 2 + 1] + bb) * ss + tt, 0.0f);
            H2[o * STR + nt * 8 + qlane * 2 + 0] = to_tf32(v0);
            H2[o * STR + nt * 8 + qlane * 2 + 1] = to_tf32(v1);
        }
    }
}

__device__ __forceinline__ void mlp_layer3_mma(
    const float* __restrict__ bias,
    const float* __restrict__ scale,
    const float* __restrict__ shift,
    const float* H2, float* Ws,
    float* __restrict__ outF, int b, int m0)
{
    const int tid   = threadIdx.x;
    const int wid   = tid >> 5;
    const int lane  = tid & 31;
    const int qid   = lane >> 2;
    const int qlane = lane & 3;

    float acc[2][8][4];
#pragma unroll
    for (int mt = 0; mt < 2; ++mt)
#pragma unroll
        for (int nt = 0; nt < 8; ++nt)
#pragma unroll
            for (int c = 0; c < 4; ++c) acc[mt][nt][c] = 0.0f;

    for (int kc = 0; kc < 128; kc += 32) {
        __syncthreads();
        for (int e = tid; e < 32 * 256; e += 256) {
            int k = e >> 8, o = e & 255;
            Ws[k * WPAD + o] = g_Wt2[(kc + k) * 256 + o];
        }
        __syncthreads();
#pragma unroll
        for (int ks = 0; ks < 4; ++ks) {
            const int kb = ks * 8 + qlane;
            uint32_t bfr[8][2];
            const float* h0 = H2 + (kc + kb) * STR;
            const float* h1 = H2 + (kc + kb + 4) * STR;
#pragma unroll
            for (int nt = 0; nt < 8; ++nt) {
                int n = nt * 8 + qid;
                bfr[nt][0] = __float_as_uint(h0[n]);
                bfr[nt][1] = __float_as_uint(h1[n]);
            }
            uint32_t afr[2][4];
            const float* w0 = Ws + kb * WPAD;
            const float* w1 = Ws + (kb + 4) * WPAD;
#pragma unroll
            for (int mt = 0; mt < 2; ++mt) {
                int m = wid * 32 + mt * 16 + qid;
                afr[mt][0] = __float_as_uint(w0[m]);
                afr[mt][1] = __float_as_uint(w0[m + 8]);
                afr[mt][2] = __float_as_uint(w1[m]);
                afr[mt][3] = __float_as_uint(w1[m + 8]);
            }
#pragma unroll
            for (int mt = 0; mt < 2; ++mt)
#pragma unroll
                for (int nt = 0; nt < 8; ++nt)
                    mma_tf32(acc[mt][nt], afr[mt], bfr[nt]);
        }
    }

#pragma unroll
    for (int mt = 0; mt < 2; ++mt) {
#pragma unroll
        for (int dr = 0; dr < 2; ++dr) {
            int o = wid * 32 + mt * 16 + qid + dr * 8;
            float bb = bias[o], ss = scale[o], tt = shift[o];
            float vA = 0.0f, vB = 0.0f;
#pragma unroll
            for (int nt = 0; nt < 8; ++nt) {
                float v0 = fmaxf((acc[mt][nt][dr * 2 + 0] + bb) * ss + tt, 0.0f);
                float v1 = fmaxf((acc[mt][nt][dr * 2 + 1] + bb) * ss + tt, 0.0f);
                float v  = fmaxf(v0, v1);
                if (nt < 4) vA = fmaxf(vA, v); else vB = fmaxf(vB, v);
            }
            vA = fmaxf(vA, __shfl_xor_sync(0xffffffffu, vA, 1));
            vA = fmaxf(vA, __shfl_xor_sync(0xffffffffu, vA, 2));
            vB = fmaxf(vB, __shfl_xor_sync(0xffffffffu, vB, 1));
            vB = fmaxf(vB, __shfl_xor_sync(0xffffffffu, vB, 2));
            if (qlane == 0) {
                outF[(b * 256 + o) * M_PTS + m0]     = vA;
                outF[(b * 256 + o) * M_PTS + m0 + 1] = vB;
            }
        }
    }
}

__global__ __launch_bounds__(256, 2) void mlp_kernel(
    const float* __restrict__ b0, const float* __restrict__ s0, const float* __restrict__ t0,
    const float* __restrict__ b1, const float* __restrict__ s1, const float* __restrict__ t1,
    const float* __restrict__ b2, const float* __restrict__ s2, const float* __restrict__ t2,
    float* __restrict__ outF)
{
    extern __shared__ float sm[];
    const int tid = threadIdx.x;
    const int b   = blockIdx.y;
    const int m0  = blockIdx.x * 2;

    int*   sIdx = (int*)(sm + OFF_SIDX);
    float* sCtr = sm + OFF_SCTR;

    if (tid < 64) sIdx[tid] = g_ball[b][m0 + (tid >> 5)][tid & 31];
    if (tid < 6)  sCtr[tid] = g_center[b][m0 + tid / 3][tid % 3];
    __syncthreads();

    {
        int col  = tid >> 2;
        int part = tid & 3;
        int p    = sIdx[col];
        int half = col >> 5;
        float cx = sCtr[half * 3 + 0];
        float cy = sCtr[half * 3 + 1];
        float cz = sCtr[half * 3 + 2];
        const float* fp = &g_featT[b][p][0];
#pragma unroll
        for (int jj = 0; jj < 18; ++jj) {
            int r = part * 18 + jj;
            float v;
            if (r == 0)      v = to_tf32(g_xyzT[b][0][p] - cx);
            else if (r == 1) v = to_tf32(g_xyzT[b][1][p] - cy);
            else if (r == 2) v = to_tf32(g_xyzT[b][2][p] - cz);
            else if (r < 67) v = to_tf32(fp[r - 3]);
            else             v = 0.0f;
            sm[OFF_XS + r * STR + col] = v;
        }
    }
    __syncthreads();

    mlp_layer1_mma(b0, s0, t0, sm + OFF_XS, sm + OFF_H1, sm + OFF_WS);
    mlp_layer2_mma(b1, s1, t1, sm + OFF_H1, sm + OFF_H2, sm + OFF_WS);
    mlp_layer3_mma(b2, s2, t2, sm + OFF_H2, sm + OFF_WS, outF, b, m0);
}

// ======================= launch =======================
extern "C" void kernel_launch(void* const* d_in, const int* in_sizes, int n_in,
                              void* d_out, int out_size) {
    const float* xyz  = (const float*)d_in[0];
    const float* feat = (const float*)d_in[1];
    const float* W0 = (const float*)d_in[2];
    const float* b0 = (const float*)d_in[3];
    const float* s0 = (const float*)d_in[4];
    const float* t0 = (const float*)d_in[5];
    const float* W1 = (const float*)d_in[6];
    const float* b1 = (const float*)d_in[7];
    const float* s1 = (const float*)d_in[8];
    const float* t1 = (const float*)d_in[9];
    const float* W2 = (const float*)d_in[10];
    const float* b2 = (const float*)d_in[11];
    const float* s2 = (const float*)d_in[12];
    const float* t2 = (const float*)d_in[13];
    float* out = (float*)d_out;

    const int fps_smem = (3 * N_PTS + 128) * sizeof(float);
    const int mlp_smem = MLP_SMEM_FLOATS * sizeof(float);
    cudaFuncSetAttribute(fps_prep_kernel, cudaFuncAttributeMaxDynamicSharedMemorySize, fps_smem);
    cudaFuncSetAttribute(mlp_kernel, cudaFuncAttributeMaxDynamicSharedMemorySize, mlp_smem);

    reset_kernel<<<1, 32>>>();
    fps_prep_kernel<<<BATCH + NPREP, 1024, fps_smem>>>(xyz, feat, W0, W1, W2, out);
    mlp_kernel<<<dim3(M_PTS / 2, BATCH), 256, mlp_smem>>>(
        b0, s0, t0, b1, s1, t1, b2, s2, t2, out + OUT_FEAT_OFF);
}

// round 16
// speedup vs baseline: 1.4082x; 1.0093x over previous
#include <cuda_runtime.h>
#include <cstdint>

#define BATCH 8
#define N_PTS 16384
#define M_PTS 1024
#define KS    32
#define CFEAT 64

#define NPREP 140     // prep/ball CTAs in the fused launch

// ---- output layout (float32): [new_xyz | new_features | indices] ----
#define OUT_XYZ_OFF  0
#define OUT_FEAT_OFF (BATCH * M_PTS * 3)                       // 24576
#define OUT_IDX_OFF  (OUT_FEAT_OFF + BATCH * 256 * M_PTS)      // 2121728

// ---- device scratch ----
__device__ float g_xyzT[BATCH][3][N_PTS];
__device__ float g_featT[BATCH][N_PTS][CFEAT];
__device__ float g_Wt0[72 * 64];            // tf32-rounded at prep
__device__ float g_Wt1[64 * 128];           // tf32-rounded at prep
__device__ float g_Wt2[128 * 256];          // tf32-rounded at prep
__device__ int   g_ball[BATCH][M_PTS][KS];
__device__ float g_center[BATCH][M_PTS][3];

// producer->consumer state (zero at module load; re-zeroed by mlp_kernel tail)
__device__ unsigned g_fps_progress[BATCH];
__device__ unsigned g_prep_done;

// exact (non-FMA) squared distance, left-to-right sum — must match XLA
__device__ __forceinline__ float sqdist(float dx, float dy, float dz) {
    float d = __fmul_rn(dx, dx);
    d = __fadd_rn(d, __fmul_rn(dy, dy));
    d = __fadd_rn(d, __fmul_rn(dz, dz));
    return d;
}

// ---- packed f32x2 helpers ----
__device__ __forceinline__ unsigned long long pk2(float a, float b) {
    unsigned long long r;
    asm("mov.b64 %0, {%1, %2};" : "=l"(r) : "f"(a), "f"(b));
    return r;
}
__device__ __forceinline__ void upk2(unsigned long long v, float& a, float& b) {
    asm("mov.b64 {%0, %1}, %2;" : "=f"(a), "=f"(b) : "l"(v));
}
__device__ __forceinline__ unsigned long long add2(unsigned long long a, unsigned long long b) {
    unsigned long long r;
    asm("add.rn.f32x2 %0, %1, %2;" : "=l"(r) : "l"(a), "l"(b));
    return r;
}
__device__ __forceinline__ unsigned long long mul2(unsigned long long a, unsigned long long b) {
    unsigned long long r;
    asm("mul.rn.f32x2 %0, %1, %2;" : "=l"(r) : "l"(a), "l"(b));
    return r;
}

// ---- tf32 helpers ----
__device__ __forceinline__ float to_tf32(float x) {
    uint32_t u;
    asm("cvt.rna.tf32.f32 %0, %1;" : "=r"(u) : "f"(x));
    return __uint_as_float(u);
}
__device__ __forceinline__ void mma_tf32(float* d, const uint32_t* a, const uint32_t* b) {
    asm volatile(
        "mma.sync.aligned.m16n8k8.row.col.f32.tf32.tf32.f32 "
        "{%0,%1,%2,%3}, {%4,%5,%6,%7}, {%8,%9}, {%0,%1,%2,%3};"
        : "+f"(d[0]), "+f"(d[1]), "+f"(d[2]), "+f"(d[3])
        : "r"(a[0]), "r"(a[1]), "r"(a[2]), "r"(a[3]), "r"(b[0]), "r"(b[1]));
}

// ---- release/acquire ----
__device__ __forceinline__ void st_release_u32(unsigned* p, unsigned v) {
    asm volatile("st.release.gpu.global.u32 [%0], %1;" :: "l"(p), "r"(v) : "memory");
}
__device__ __forceinline__ unsigned ld_acquire_u32(const unsigned* p) {
    unsigned v;
    asm volatile("ld.acquire.gpu.global.u32 %0, [%1];" : "=r"(v) : "l"(p) : "memory");
    return v;
}

// ======================= fused FPS + prep + ball =======================
__global__ __launch_bounds__(1024, 1) void fps_prep_kernel(
    const float* __restrict__ xyz, const float* __restrict__ feat,
    const float* __restrict__ W0, const float* __restrict__ W1,
    const float* __restrict__ W2, float* __restrict__ out)
{
    extern __shared__ float sm[];

    if (blockIdx.x >= BATCH) {
        // ---------------- prep branch ----------------
        const int gtid   = (blockIdx.x - BATCH) * 1024 + threadIdx.x;
        const int stride = NPREP * 1024;

        for (int id = gtid; id < 72 * 64 + 64 * 128 + 128 * 256; id += stride) {
            if (id < 72 * 64) {
                int c = id >> 6, o = id & 63;
                g_Wt0[id] = (c < 67) ? to_tf32(W0[o * 67 + c]) : 0.0f;
            } else if (id < 72 * 64 + 64 * 128) {
                int e = id - 72 * 64;
                int c = e >> 7, o = e & 127;
                g_Wt1[e] = to_tf32(W1[o * 64 + c]);
            } else {
                int e = id - 72 * 64 - 64 * 128;
                int c = e >> 8, o = e & 255;
                g_Wt2[e] = to_tf32(W2[o * 128 + c]);
            }
        }
        for (int id = gtid; id < BATCH * 3 * N_PTS; id += stride) {
            int b = id / (3 * N_PTS);
            int r = id % (3 * N_PTS);
            int c = r / N_PTS;
            int n = r % N_PTS;
            g_xyzT[b][c][n] = xyz[(b * N_PTS + n) * 3 + c];
        }
        const float4* f4 = (const float4*)feat;
        for (int id = gtid; id < (BATCH * CFEAT * N_PTS) / 4; id += stride) {
            float4 v = f4[id];
            int lin = id * 4;
            int b = lin >> 20;
            int r = lin & 0xFFFFF;
            int c = r >> 14;
            int n = r & 16383;
            g_featT[b][n + 0][c] = v.x;
            g_featT[b][n + 1][c] = v.y;
            g_featT[b][n + 2][c] = v.z;
            g_featT[b][n + 3][c] = v.w;
        }

        __syncthreads();
        if (threadIdx.x == 0) {
            __threadfence();
            atomicAdd(&g_prep_done, 1u);
            while (ld_acquire_u32(&g_prep_done) < (unsigned)NPREP) __nanosleep(200);
        }
        __syncthreads();

        // ---------------- ball branch ----------------
        const int wid  = threadIdx.x >> 5;
        const int lane = threadIdx.x & 31;
        int* bufs = (int*)sm;                                   // [32][32]
        volatile unsigned* s_prog = (volatile unsigned*)(bufs + 32 * 32);

        if (wid == 0) {
            if (lane < BATCH) s_prog[lane] = 0u;
            __syncwarp();
            for (;;) {
                unsigned p = (lane < BATCH) ? ld_acquire_u32(&g_fps_progress[lane]) : M_PTS;
                if (lane < BATCH) s_prog[lane] = p;
                unsigned donemask = __ballot_sync(0xffffffffu, p >= (unsigned)M_PTS);
                if (donemask == 0xffffffffu) break;
                __nanosleep(1000);
            }
            return;
        }
        const int worker = (blockIdx.x - BATCH) * 31 + (wid - 1);
        int* bufw = bufs + wid * 32;

        for (int q = worker; q < BATCH * M_PTS; q += NPREP * 31) {
            const int b = q & 7;
            const int m = q >> 3;

            for (;;) {
                unsigned p = s_prog[b];
                if (p > (unsigned)m && p <= (unsigned)M_PTS) {
                    if (ld_acquire_u32(&g_fps_progress[b]) > (unsigned)m) break;
                }
                __nanosleep(400);
            }

            const float cx = g_center[b][m][0];
            const float cy = g_center[b][m][1];
            const float cz = g_center[b][m][2];
            const float* __restrict__ px = g_xyzT[b][0];
            const float* __restrict__ py = g_xyzT[b][1];
            const float* __restrict__ pz = g_xyzT[b][2];

            int count = 0;
            for (int n0 = 0; n0 < N_PTS; n0 += 32) {
                int i = n0 + lane;
                float dx = px[i] - cx;
                float dy = py[i] - cy;
                float dz = pz[i] - cz;
                float d  = sqdist(dx, dy, dz);
                bool pr  = (d <= 0.16f);
                unsigned mask = __ballot_sync(0xffffffffu, pr);
                int pos = count + __popc(mask & ((1u << lane) - 1u));
                if (pr && pos < 32) bufw[pos] = i;
                count += __popc(mask);
                if (count >= 32) break;
            }
            __syncwarp();
            int first = bufw[0];
            int v = (lane < count) ? bufw[lane] : first;
            g_ball[b][m][lane] = v;
            __syncwarp();
        }
        return;
    }

    // ---------------- FPS branch (R14 loop + predicated argmax scan) ----------------
    float* sx = sm;
    float* sy = sm + N_PTS;
    float* zp = sm + 2 * N_PTS;
    unsigned* rv = (unsigned*)(sm + 3 * N_PTS);   // [2][32]
    unsigned* ri = rv + 64;                        // [2][32]

    const int b    = blockIdx.x;
    const int tid  = threadIdx.x;
    const int lane = tid & 31;
    const int wid  = tid >> 5;

    const float* gx = xyz + b * N_PTS * 3;
    for (int t = tid; t < N_PTS; t += 1024) {
        float x = gx[3 * t + 0];
        float y = gx[3 * t + 1];
        float z = gx[3 * t + 2];
        sx[t] = x;
        sy[t] = y;
        int k = t >> 10, tt = t & 1023;
        zp[(((k >> 1) * 1024) + tt) * 2 + (k & 1)] = z;
    }
    __syncthreads();

    unsigned long long xx2[8], yy2[8];
    float dist[16];
#pragma unroll
    for (int j = 0; j < 8; ++j) {
        xx2[j] = pk2(sx[(2 * j) * 1024 + tid], sx[(2 * j + 1) * 1024 + tid]);
        yy2[j] = pk2(sy[(2 * j) * 1024 + tid], sy[(2 * j + 1) * 1024 + tid]);
    }
#pragma unroll
    for (int k = 0; k < 16; ++k) dist[k] = 1e10f;

    float cx = sx[0], cy = sy[0], cz = zp[0];
    int   cidx = 0;

    const unsigned long long* zp64 = (const unsigned long long*)zp;

    for (int it = 0; it < M_PTS; ++it) {
        if (tid == 0) {
            out[OUT_XYZ_OFF + (b * M_PTS + it) * 3 + 0] = cx;
            out[OUT_XYZ_OFF + (b * M_PTS + it) * 3 + 1] = cy;
            out[OUT_XYZ_OFF + (b * M_PTS + it) * 3 + 2] = cz;
            out[OUT_IDX_OFF + b * M_PTS + it] = (float)cidx;
            g_center[b][it][0] = cx;
            g_center[b][it][1] = cy;
            g_center[b][it][2] = cz;
            st_release_u32(&g_fps_progress[b], (unsigned)(it + 1));
        }
        if (it == M_PTS - 1) break;

        const unsigned long long ncx = pk2(-cx, -cx);
        const unsigned long long ncy = pk2(-cy, -cy);
        const unsigned long long ncz = pk2(-cz, -cz);

        float mx = -1.0f;
#pragma unroll
        for (int j = 0; j < 8; ++j) {
            unsigned long long zz = zp64[j * 1024 + tid];
            unsigned long long dx = add2(xx2[j], ncx);
            unsigned long long dy = add2(yy2[j], ncy);
            unsigned long long dz = add2(zz,     ncz);
            unsigned long long s  = add2(add2(mul2(dx, dx), mul2(dy, dy)), mul2(dz, dz));
            float d0, d1;
            upk2(s, d0, d1);
            float n0 = fminf(dist[2 * j + 0], d0);
            float n1 = fminf(dist[2 * j + 1], d1);
            dist[2 * j + 0] = n0;
            dist[2 * j + 1] = n1;
            mx = fmaxf(mx, fmaxf(n0, n1));
        }

        // warp max FIRST; only potential winners run the 16-slot scan
        const int par = (it & 1) * 32;
        unsigned mxb  = __float_as_uint(mx);
        unsigned wmax = __reduce_max_sync(0xffffffffu, mxb);
        unsigned cand = 0xffffffffu;
        if (mxb == wmax) {
            int bk = 0;
#pragma unroll
            for (int k = 15; k >= 0; --k)
                if (dist[k] == mx) bk = k;
            cand = (unsigned)(bk * 1024 + tid);
        }
        unsigned wi = __reduce_min_sync(0xffffffffu, cand);
        if (lane == 0) { rv[par + wid] = wmax; ri[par + wid] = wi; }
        __syncthreads();

        unsigned v    = rv[par + lane];
        unsigned i    = ri[par + lane];
        unsigned bmax = __reduce_max_sync(0xffffffffu, v);
        unsigned c2   = (v == bmax) ? i : 0xffffffffu;
        unsigned gi   = __reduce_min_sync(0xffffffffu, c2);
        {
            int p = (int)gi;
            int k = p >> 10, tt = p & 1023;
            cx = sx[p];
            cy = sy[p];
            cz = zp[(((k >> 1) * 1024) + tt) * 2 + (k & 1)];
            cidx = p;
        }
    }
}

// ======================= fused MLP + maxpool (all-tf32 mma) =======================
#define STR 72
#define WPAD 264
#define W0STR 72
#define OFF_XS  0
#define OFF_H1  (OFF_XS + 72 * STR)
#define OFF_H2  (OFF_H1 + 64 * STR)
#define OFF_WS  (OFF_H2 + 128 * STR)
#define OFF_SIDX (OFF_WS + 32 * WPAD)
#define OFF_SCTR (OFF_SIDX + 64)
#define MLP_SMEM_FLOATS (OFF_SCTR + 8)

__device__ __forceinline__ void mlp_layer1_mma(
    const float* __restrict__ bias,
    const float* __restrict__ scale,
    const float* __restrict__ shift,
    const float* X, float* H1, float* Ws)
{
    const int tid   = threadIdx.x;
    const int wid   = tid >> 5;
    const int lane  = tid & 31;
    const int qid   = lane >> 2;
    const int qlane = lane & 3;
    const int mw    = wid & 3;
    const int nh    = wid >> 2;

    for (int e = tid; e < 72 * 64; e += 256) {
        int k = e >> 6, o = e & 63;
        Ws[k * W0STR + o] = g_Wt0[e];
    }
    __syncthreads();

    float acc[4][4];
#pragma unroll
    for (int nt = 0; nt < 4; ++nt)
#pragma unroll
        for (int c = 0; c < 4; ++c) acc[nt][c] = 0.0f;

#pragma unroll
    for (int ks = 0; ks < 9; ++ks) {
        const int kb = ks * 8 + qlane;
        uint32_t bfr[4][2];
        const float* x0 = X + kb * STR;
        const float* x1 = X + (kb + 4) * STR;
#pragma unroll
        for (int nt = 0; nt < 4; ++nt) {
            int n = nh * 32 + nt * 8 + qid;
            bfr[nt][0] = __float_as_uint(x0[n]);
            bfr[nt][1] = __float_as_uint(x1[n]);
        }
        uint32_t afr[4];
        const float* w0 = Ws + kb * W0STR;
        const float* w1 = Ws + (kb + 4) * W0STR;
        int m = mw * 16 + qid;
        afr[0] = __float_as_uint(w0[m]);
        afr[1] = __float_as_uint(w0[m + 8]);
        afr[2] = __float_as_uint(w1[m]);
        afr[3] = __float_as_uint(w1[m + 8]);
#pragma unroll
        for (int nt = 0; nt < 4; ++nt)
            mma_tf32(acc[nt], afr, bfr[nt]);
    }
    __syncthreads();

#pragma unroll
    for (int dr = 0; dr < 2; ++dr) {
        int o = mw * 16 + qid + dr * 8;
        float bb = bias[o], ss = scale[o], tt = shift[o];
#pragma unroll
        for (int nt = 0; nt < 4; ++nt) {
            float v0 = fmaxf((acc[nt][dr * 2 + 0] + bb) * ss + tt, 0.0f);
            float v1 = fmaxf((acc[nt][dr * 2 + 1] + bb) * ss + tt, 0.0f);
            int n = nh * 32 + nt * 8 + qlane * 2;
            H1[o * STR + n + 0] = to_tf32(v0);
            H1[o * STR + n + 1] = to_tf32(v1);
        }
    }
}

__device__ __forceinline__ void mlp_layer2_mma(
    const float* __restrict__ bias,
    const float* __restrict__ scale,
    const float* __restrict__ shift,
    const float* H1, float* H2, float* Ws)
{
    const int tid   = threadIdx.x;
    const int wid   = tid >> 5;
    const int lane  = tid & 31;
    const int qid   = lane >> 2;
    const int qlane = lane & 3;

    float acc[8][4];
#pragma unroll
    for (int nt = 0; nt < 8; ++nt)
#pragma unroll
        for (int c = 0; c < 4; ++c) acc[nt][c] = 0.0f;

    for (int kc = 0; kc < 64; kc += 32) {
        __syncthreads();
        for (int e = tid; e < 32 * 128; e += 256) {
            int k = e >> 7, o = e & 127;
            Ws[k * WPAD + o] = g_Wt1[(kc + k) * 128 + o];
        }
        __syncthreads();
#pragma unroll
        for (int ks = 0; ks < 4; ++ks) {
            const int kb = ks * 8 + qlane;
            uint32_t bfr[8][2];
            const float* h0 = H1 + (kc + kb) * STR;
            const float* h1 = H1 + (kc + kb + 4) * STR;
#pragma unroll
            for (int nt = 0; nt < 8; ++nt) {
                int n = nt * 8 + qid;
                bfr[nt][0] = __float_as_uint(h0[n]);
                bfr[nt][1] = __float_as_uint(h1[n]);
            }
            uint32_t afr[4];
            const float* w0 = Ws + kb * WPAD;
            const float* w1 = Ws + (kb + 4) * WPAD;
            int m = wid * 16 + qid;
            afr[0] = __float_as_uint(w0[m]);
            afr[1] = __float_as_uint(w0[m + 8]);
            afr[2] = __float_as_uint(w1[m]);
            afr[3] = __float_as_uint(w1[m + 8]);
#pragma unroll
            for (int nt = 0; nt < 8; ++nt)
                mma_tf32(acc[nt], afr, bfr[nt]);
        }
    }
    __syncthreads();

#pragma unroll
    for (int dr = 0; dr < 2; ++dr) {
        int o = wid * 16 + qid + dr * 8;
        float bb = bias[o], ss = scale[o], tt = shift[o];
#pragma unroll
        for (int nt = 0; nt < 8; ++nt) {
            float v0 = fmaxf((acc[nt][dr * 2 + 0] + bb) * ss + tt, 0.0f);
            float v1 = fmaxf((acc[nt][dr * 2 + 1] + bb) * ss + tt, 0.0f);
            H2[o * STR + nt * 8 + qlane * 2 + 0] = to_tf32(v0);
            H2[o * STR + nt * 8 + qlane * 2 + 1] = to_tf32(v1);
        }
    }
}

__device__ __forceinline__ void mlp_layer3_mma(
    const float* __restrict__ bias,
    const float* __restrict__ scale,
    const float* __restrict__ shift,
    const float* H2, float* Ws,
    float* __restrict__ outF, int b, int m0)
{
    const int tid   = threadIdx.x;
    const int wid   = tid >> 5;
    const int lane  = tid & 31;
    const int qid   = lane >> 2;
    const int qlane = lane & 3;

    float acc[2][8][4];
#pragma unroll
    for (int mt = 0; mt < 2; ++mt)
#pragma unroll
        for (int nt = 0; nt < 8; ++nt)
#pragma unroll
            for (int c = 0; c < 4; ++c) acc[mt][nt][c] = 0.0f;

    for (int kc = 0; kc < 128; kc += 32) {
        __syncthreads();
        for (int e = tid; e < 32 * 256; e += 256) {
            int k = e >> 8, o = e & 255;
            Ws[k * WPAD + o] = g_Wt2[(kc + k) * 256 + o];
        }
        __syncthreads();
#pragma unroll
        for (int ks = 0; ks < 4; ++ks) {
            const int kb = ks * 8 + qlane;
            uint32_t bfr[8][2];
            const float* h0 = H2 + (kc + kb) * STR;
            const float* h1 = H2 + (kc + kb + 4) * STR;
#pragma unroll
            for (int nt = 0; nt < 8; ++nt) {
                int n = nt * 8 + qid;
                bfr[nt][0] = __float_as_uint(h0[n]);
                bfr[nt][1] = __float_as_uint(h1[n]);
            }
            uint32_t afr[2][4];
            const float* w0 = Ws + kb * WPAD;
            const float* w1 = Ws + (kb + 4) * WPAD;
#pragma unroll
            for (int mt = 0; mt < 2; ++mt) {
                int m = wid * 32 + mt * 16 + qid;
                afr[mt][0] = __float_as_uint(w0[m]);
                afr[mt][1] = __float_as_uint(w0[m + 8]);
                afr[mt][2] = __float_as_uint(w1[m]);
                afr[mt][3] = __float_as_uint(w1[m + 8]);
            }
#pragma unroll
            for (int mt = 0; mt < 2; ++mt)
#pragma unroll
                for (int nt = 0; nt < 8; ++nt)
                    mma_tf32(acc[mt][nt], afr[mt], bfr[nt]);
        }
    }

#pragma unroll
    for (int mt = 0; mt < 2; ++mt) {
#pragma unroll
        for (int dr = 0; dr < 2; ++dr) {
            int o = wid * 32 + mt * 16 + qid + dr * 8;
            float bb = bias[o], ss = scale[o], tt = shift[o];
            float vA = 0.0f, vB = 0.0f;
#pragma unroll
            for (int nt = 0; nt < 8; ++nt) {
                float v0 = fmaxf((acc[mt][nt][dr * 2 + 0] + bb) * ss + tt, 0.0f);
                float v1 = fmaxf((acc[mt][nt][dr * 2 + 1] + bb) * ss + tt, 0.0f);
                float v  = fmaxf(v0, v1);
                if (nt < 4) vA = fmaxf(vA, v); else vB = fmaxf(vB, v);
            }
            vA = fmaxf(vA, __shfl_xor_sync(0xffffffffu, vA, 1));
            vA = fmaxf(vA, __shfl_xor_sync(0xffffffffu, vA, 2));
            vB = fmaxf(vB, __shfl_xor_sync(0xffffffffu, vB, 1));
            vB = fmaxf(vB, __shfl_xor_sync(0xffffffffu, vB, 2));
            if (qlane == 0) {
                outF[(b * 256 + o) * M_PTS + m0]     = vA;
                outF[(b * 256 + o) * M_PTS + m0 + 1] = vB;
            }
        }
    }
}

__global__ __launch_bounds__(256, 2) void mlp_kernel(
    const float* __restrict__ b0, const float* __restrict__ s0, const float* __restrict__ t0,
    const float* __restrict__ b1, const float* __restrict__ s1, const float* __restrict__ t1,
    const float* __restrict__ b2, const float* __restrict__ s2, const float* __restrict__ t2,
    float* __restrict__ outF)
{
    extern __shared__ float sm[];
    const int tid = threadIdx.x;
    const int b   = blockIdx.y;
    const int m0  = blockIdx.x * 2;

    // fold the flag reset for the NEXT launch into this kernel (runs after
    // all flag consumers; stream order makes this safe; zero-init covers run 1)
    if (blockIdx.x == 0 && blockIdx.y == 0 && tid < BATCH + 1) {
        if (tid < BATCH) g_fps_progress[tid] = 0u;
        else g_prep_done = 0u;
    }

    int*   sIdx = (int*)(sm + OFF_SIDX);
    float* sCtr = sm + OFF_SCTR;

    if (tid < 64) sIdx[tid] = g_ball[b][m0 + (tid >> 5)][tid & 31];
    if (tid < 6)  sCtr[tid] = g_center[b][m0 + tid / 3][tid % 3];
    __syncthreads();

    {
        int col  = tid >> 2;
        int part = tid & 3;
        int p    = sIdx[col];
        int half = col >> 5;
        float cx = sCtr[half * 3 + 0];
        float cy = sCtr[half * 3 + 1];
        float cz = sCtr[half * 3 + 2];
        const float* fp = &g_featT[b][p][0];
#pragma unroll
        for (int jj = 0; jj < 18; ++jj) {
            int r = part * 18 + jj;
            float v;
            if (r == 0)      v = to_tf32(g_xyzT[b][0][p] - cx);
            else if (r == 1) v = to_tf32(g_xyzT[b][1][p] - cy);
            else if (r == 2) v = to_tf32(g_xyzT[b][2][p] - cz);
            else if (r < 67) v = to_tf32(fp[r - 3]);
            else             v = 0.0f;
            sm[OFF_XS + r * STR + col] = v;
        }
    }
    __syncthreads();

    mlp_layer1_mma(b0, s0, t0, sm + OFF_XS, sm + OFF_H1, sm + OFF_WS);
    mlp_layer2_mma(b1, s1, t1, sm + OFF_H1, sm + OFF_H2, sm + OFF_WS);
    mlp_layer3_mma(b2, s2, t2, sm + OFF_H2, sm + OFF_WS, outF, b, m0);
}

// ======================= launch =======================
extern "C" void kernel_launch(void* const* d_in, const int* in_sizes, int n_in,
                              void* d_out, int out_size) {
    const float* xyz  = (const float*)d_in[0];
    const float* feat = (const float*)d_in[1];
    const float* W0 = (const float*)d_in[2];
    const float* b0 = (const float*)d_in[3];
    const float* s0 = (const float*)d_in[4];
    const float* t0 = (const float*)d_in[5];
    const float* W1 = (const float*)d_in[6];
    const float* b1 = (const float*)d_in[7];
    const float* s1 = (const float*)d_in[8];
    const float* t1 = (const float*)d_in[9];
    const float* W2 = (const float*)d_in[10];
    const float* b2 = (const float*)d_in[11];
    const float* s2 = (const float*)d_in[12];
    const float* t2 = (const float*)d_in[13];
    float* out = (float*)d_out;

    const int fps_smem = (3 * N_PTS + 128) * sizeof(float);
    const int mlp_smem = MLP_SMEM_FLOATS * sizeof(float);
    cudaFuncSetAttribute(fps_prep_kernel, cudaFuncAttributeMaxDynamicSharedMemorySize, fps_smem);
    cudaFuncSetAttribute(mlp_kernel, cudaFuncAttributeMaxDynamicSharedMemorySize, mlp_smem);

    fps_prep_kernel<<<BATCH + NPREP, 1024, fps_smem>>>(xyz, feat, W0, W1, W2, out);
    mlp_kernel<<<dim3(M_PTS / 2, BATCH), 256, mlp_smem>>>(
        b0, s0, t0, b1, s1, t1, b2, s2, t2, out + OUT_FEAT_OFF);
}

// round 17
// speedup vs baseline: 1.5075x; 1.0705x over previous
#include <cuda_runtime.h>
#include <cstdint>

#define BATCH 8
#define N_PTS 16384
#define M_PTS 1024
#define KS    32
#define CFEAT 64

#define NPREP 140     // prep/ball CTAs in the fused launch

// ---- output layout (float32): [new_xyz | new_features | indices] ----
#define OUT_XYZ_OFF  0
#define OUT_FEAT_OFF (BATCH * M_PTS * 3)                       // 24576
#define OUT_IDX_OFF  (OUT_FEAT_OFF + BATCH * 256 * M_PTS)      // 2121728

// ---- device scratch ----
__device__ float g_xyzT[BATCH][3][N_PTS];
__device__ float g_featT[BATCH][N_PTS][CFEAT];
__device__ float g_Wt0[72 * 64];            // tf32-rounded at prep
__device__ float g_Wt1[64 * 128];           // tf32-rounded at prep
__device__ float g_Wt2[128 * 256];          // tf32-rounded at prep
__device__ int   g_ball[BATCH][M_PTS][KS];
__device__ float g_center[BATCH][M_PTS][3];

// producer->consumer state (zero at module load; re-zeroed by mlp_kernel tail)
__device__ unsigned g_fps_progress[BATCH];
__device__ unsigned g_prep_done;

// exact (non-FMA) squared distance, left-to-right sum — must match XLA
__device__ __forceinline__ float sqdist(float dx, float dy, float dz) {
    float d = __fmul_rn(dx, dx);
    d = __fadd_rn(d, __fmul_rn(dy, dy));
    d = __fadd_rn(d, __fmul_rn(dz, dz));
    return d;
}

// ---- packed f32x2 helpers ----
__device__ __forceinline__ unsigned long long pk2(float a, float b) {
    unsigned long long r;
    asm("mov.b64 %0, {%1, %2};" : "=l"(r) : "f"(a), "f"(b));
    return r;
}
__device__ __forceinline__ void upk2(unsigned long long v, float& a, float& b) {
    asm("mov.b64 {%0, %1}, %2;" : "=f"(a), "=f"(b) : "l"(v));
}
__device__ __forceinline__ unsigned long long add2(unsigned long long a, unsigned long long b) {
    unsigned long long r;
    asm("add.rn.f32x2 %0, %1, %2;" : "=l"(r) : "l"(a), "l"(b));
    return r;
}
__device__ __forceinline__ unsigned long long mul2(unsigned long long a, unsigned long long b) {
    unsigned long long r;
    asm("mul.rn.f32x2 %0, %1, %2;" : "=l"(r) : "l"(a), "l"(b));
    return r;
}

// ---- tf32 helpers ----
__device__ __forceinline__ float to_tf32(float x) {
    uint32_t u;
    asm("cvt.rna.tf32.f32 %0, %1;" : "=r"(u) : "f"(x));
    return __uint_as_float(u);
}
__device__ __forceinline__ void mma_tf32(float* d, const uint32_t* a, const uint32_t* b) {
    asm volatile(
        "mma.sync.aligned.m16n8k8.row.col.f32.tf32.tf32.f32 "
        "{%0,%1,%2,%3}, {%4,%5,%6,%7}, {%8,%9}, {%0,%1,%2,%3};"
        : "+f"(d[0]), "+f"(d[1]), "+f"(d[2]), "+f"(d[3])
        : "r"(a[0]), "r"(a[1]), "r"(a[2]), "r"(a[3]), "r"(b[0]), "r"(b[1]));
}

// ---- release/acquire ----
__device__ __forceinline__ void st_release_u32(unsigned* p, unsigned v) {
    asm volatile("st.release.gpu.global.u32 [%0], %1;" :: "l"(p), "r"(v) : "memory");
}
__device__ __forceinline__ unsigned ld_acquire_u32(const unsigned* p) {
    unsigned v;
    asm volatile("ld.acquire.gpu.global.u32 %0, [%1];" : "=r"(v) : "l"(p) : "memory");
    return v;
}

// ======================= fused FPS + prep + ball =======================
__global__ __launch_bounds__(1024, 1) void fps_prep_kernel(
    const float* __restrict__ xyz, const float* __restrict__ feat,
    const float* __restrict__ W0, const float* __restrict__ W1,
    const float* __restrict__ W2, float* __restrict__ out)
{
    extern __shared__ float sm[];

    if (blockIdx.x >= BATCH) {
        // ---------------- prep branch ----------------
        const int gtid   = (blockIdx.x - BATCH) * 1024 + threadIdx.x;
        const int stride = NPREP * 1024;

        for (int id = gtid; id < 72 * 64 + 64 * 128 + 128 * 256; id += stride) {
            if (id < 72 * 64) {
                int c = id >> 6, o = id & 63;
                g_Wt0[id] = (c < 67) ? to_tf32(W0[o * 67 + c]) : 0.0f;
            } else if (id < 72 * 64 + 64 * 128) {
                int e = id - 72 * 64;
                int c = e >> 7, o = e & 127;
                g_Wt1[e] = to_tf32(W1[o * 64 + c]);
            } else {
                int e = id - 72 * 64 - 64 * 128;
                int c = e >> 8, o = e & 255;
                g_Wt2[e] = to_tf32(W2[o * 128 + c]);
            }
        }
        for (int id = gtid; id < BATCH * 3 * N_PTS; id += stride) {
            int b = id / (3 * N_PTS);
            int r = id % (3 * N_PTS);
            int c = r / N_PTS;
            int n = r % N_PTS;
            g_xyzT[b][c][n] = xyz[(b * N_PTS + n) * 3 + c];
        }
        const float4* f4 = (const float4*)feat;
        for (int id = gtid; id < (BATCH * CFEAT * N_PTS) / 4; id += stride) {
            float4 v = f4[id];
            int lin = id * 4;
            int b = lin >> 20;
            int r = lin & 0xFFFFF;
            int c = r >> 14;
            int n = r & 16383;
            g_featT[b][n + 0][c] = v.x;
            g_featT[b][n + 1][c] = v.y;
            g_featT[b][n + 2][c] = v.z;
            g_featT[b][n + 3][c] = v.w;
        }

        __syncthreads();
        if (threadIdx.x == 0) {
            __threadfence();
            atomicAdd(&g_prep_done, 1u);
            while (ld_acquire_u32(&g_prep_done) < (unsigned)NPREP) __nanosleep(200);
        }
        __syncthreads();

        // ---------------- ball branch ----------------
        const int wid  = threadIdx.x >> 5;
        const int lane = threadIdx.x & 31;
        int* bufs = (int*)sm;                                   // [32][32]
        volatile unsigned* s_prog = (volatile unsigned*)(bufs + 32 * 32);

        if (wid == 0) {
            if (lane < BATCH) s_prog[lane] = 0u;
            __syncwarp();
            for (;;) {
                unsigned p = (lane < BATCH) ? ld_acquire_u32(&g_fps_progress[lane]) : M_PTS;
                if (lane < BATCH) s_prog[lane] = p;
                unsigned donemask = __ballot_sync(0xffffffffu, p >= (unsigned)M_PTS);
                if (donemask == 0xffffffffu) break;
                __nanosleep(1000);
            }
            return;
        }
        const int worker = (blockIdx.x - BATCH) * 31 + (wid - 1);
        int* bufw = bufs + wid * 32;

        for (int q = worker; q < BATCH * M_PTS; q += NPREP * 31) {
            const int b = q & 7;
            const int m = q >> 3;

            for (;;) {
                unsigned p = s_prog[b];
                if (p > (unsigned)m && p <= (unsigned)M_PTS) {
                    if (ld_acquire_u32(&g_fps_progress[b]) > (unsigned)m) break;
                }
                __nanosleep(400);
            }

            const float cx = g_center[b][m][0];
            const float cy = g_center[b][m][1];
            const float cz = g_center[b][m][2];
            const float* __restrict__ px = g_xyzT[b][0];
            const float* __restrict__ py = g_xyzT[b][1];
            const float* __restrict__ pz = g_xyzT[b][2];

            int count = 0;
            for (int n0 = 0; n0 < N_PTS; n0 += 32) {
                int i = n0 + lane;
                float dx = px[i] - cx;
                float dy = py[i] - cy;
                float dz = pz[i] - cz;
                float d  = sqdist(dx, dy, dz);
                bool pr  = (d <= 0.16f);
                unsigned mask = __ballot_sync(0xffffffffu, pr);
                int pos = count + __popc(mask & ((1u << lane) - 1u));
                if (pr && pos < 32) bufw[pos] = i;
                count += __popc(mask);
                if (count >= 32) break;
            }
            __syncwarp();
            int first = bufw[0];
            int v = (lane < count) ? bufw[lane] : first;
            g_ball[b][m][lane] = v;
            __syncwarp();
        }
        return;
    }

    // ---------------- FPS branch (R16 — known good) ----------------
    float* sx = sm;
    float* sy = sm + N_PTS;
    float* zp = sm + 2 * N_PTS;
    unsigned* rv = (unsigned*)(sm + 3 * N_PTS);   // [2][32]
    unsigned* ri = rv + 64;                        // [2][32]

    const int b    = blockIdx.x;
    const int tid  = threadIdx.x;
    const int lane = tid & 31;
    const int wid  = tid >> 5;

    const float* gx = xyz + b * N_PTS * 3;
    for (int t = tid; t < N_PTS; t += 1024) {
        float x = gx[3 * t + 0];
        float y = gx[3 * t + 1];
        float z = gx[3 * t + 2];
        sx[t] = x;
        sy[t] = y;
        int k = t >> 10, tt = t & 1023;
        zp[(((k >> 1) * 1024) + tt) * 2 + (k & 1)] = z;
    }
    __syncthreads();

    unsigned long long xx2[8], yy2[8];
    float dist[16];
#pragma unroll
    for (int j = 0; j < 8; ++j) {
        xx2[j] = pk2(sx[(2 * j) * 1024 + tid], sx[(2 * j + 1) * 1024 + tid]);
        yy2[j] = pk2(sy[(2 * j) * 1024 + tid], sy[(2 * j + 1) * 1024 + tid]);
    }
#pragma unroll
    for (int k = 0; k < 16; ++k) dist[k] = 1e10f;

    float cx = sx[0], cy = sy[0], cz = zp[0];
    int   cidx = 0;

    const unsigned long long* zp64 = (const unsigned long long*)zp;

    for (int it = 0; it < M_PTS; ++it) {
        if (tid == 0) {
            out[OUT_XYZ_OFF + (b * M_PTS + it) * 3 + 0] = cx;
            out[OUT_XYZ_OFF + (b * M_PTS + it) * 3 + 1] = cy;
            out[OUT_XYZ_OFF + (b * M_PTS + it) * 3 + 2] = cz;
            out[OUT_IDX_OFF + b * M_PTS + it] = (float)cidx;
            g_center[b][it][0] = cx;
            g_center[b][it][1] = cy;
            g_center[b][it][2] = cz;
            st_release_u32(&g_fps_progress[b], (unsigned)(it + 1));
        }
        if (it == M_PTS - 1) break;

        const unsigned long long ncx = pk2(-cx, -cx);
        const unsigned long long ncy = pk2(-cy, -cy);
        const unsigned long long ncz = pk2(-cz, -cz);

        float mx = -1.0f;
#pragma unroll
        for (int j = 0; j < 8; ++j) {
            unsigned long long zz = zp64[j * 1024 + tid];
            unsigned long long dx = add2(xx2[j], ncx);
            unsigned long long dy = add2(yy2[j], ncy);
            unsigned long long dz = add2(zz,     ncz);
            unsigned long long s  = add2(add2(mul2(dx, dx), mul2(dy, dy)), mul2(dz, dz));
            float d0, d1;
            upk2(s, d0, d1);
            float n0 = fminf(dist[2 * j + 0], d0);
            float n1 = fminf(dist[2 * j + 1], d1);
            dist[2 * j + 0] = n0;
            dist[2 * j + 1] = n1;
            mx = fmaxf(mx, fmaxf(n0, n1));
        }

        const int par = (it & 1) * 32;
        unsigned mxb  = __float_as_uint(mx);
        unsigned wmax = __reduce_max_sync(0xffffffffu, mxb);
        unsigned cand = 0xffffffffu;
        if (mxb == wmax) {
            int bk = 0;
#pragma unroll
            for (int k = 15; k >= 0; --k)
                if (dist[k] == mx) bk = k;
            cand = (unsigned)(bk * 1024 + tid);
        }
        unsigned wi = __reduce_min_sync(0xffffffffu, cand);
        if (lane == 0) { rv[par + wid] = wmax; ri[par + wid] = wi; }
        __syncthreads();

        unsigned v    = rv[par + lane];
        unsigned i    = ri[par + lane];
        unsigned bmax = __reduce_max_sync(0xffffffffu, v);
        unsigned c2   = (v == bmax) ? i : 0xffffffffu;
        unsigned gi   = __reduce_min_sync(0xffffffffu, c2);
        {
            int p = (int)gi;
            int k = p >> 10, tt = p & 1023;
            cx = sx[p];
            cy = sy[p];
            cz = zp[(((k >> 1) * 1024) + tt) * 2 + (k & 1)];
            cidx = p;
        }
    }
}

// ======================= fused MLP + maxpool (tf32 mma, direct weight LDG) =======================
#define STR 72
#define OFF_XS  0
#define OFF_H1  (OFF_XS + 72 * STR)      // 5184
#define OFF_H2  (OFF_H1 + 64 * STR)      // 9792
#define OFF_SIDX (OFF_H2 + 128 * STR)    // 19008
#define OFF_SCTR (OFF_SIDX + 64)
#define MLP_SMEM_FLOATS (OFF_SCTR + 8)   // 19080 floats = 76.3 KB

// Layer 1: CIN=72 (padded), COUT=64, 64 cols. 8 warps: mw=wid&3 (M16), nh=wid>>2 (N32).
__device__ __forceinline__ void mlp_layer1_mma(
    const float* __restrict__ bias,
    const float* __restrict__ scale,
    const float* __restrict__ shift,
    const float* X, float* H1)
{
    const int tid   = threadIdx.x;
    const int wid   = tid >> 5;
    const int lane  = tid & 31;
    const int qid   = lane >> 2;
    const int qlane = lane & 3;
    const int mw    = wid & 3;
    const int nh    = wid >> 2;

    float acc[4][4];
#pragma unroll
    for (int nt = 0; nt < 4; ++nt)
#pragma unroll
        for (int c = 0; c < 4; ++c) acc[nt][c] = 0.0f;

    const int m = mw * 16 + qid;

#pragma unroll
    for (int ks = 0; ks < 9; ++ks) {
        const int kb = ks * 8 + qlane;
        uint32_t afr[4];
        const float* w0 = g_Wt0 + kb * 64;
        const float* w1 = g_Wt0 + (kb + 4) * 64;
        afr[0] = __float_as_uint(w0[m]);
        afr[1] = __float_as_uint(w0[m + 8]);
        afr[2] = __float_as_uint(w1[m]);
        afr[3] = __float_as_uint(w1[m + 8]);
        uint32_t bfr[4][2];
        const float* x0 = X + kb * STR;
        const float* x1 = X + (kb + 4) * STR;
#pragma unroll
        for (int nt = 0; nt < 4; ++nt) {
            int n = nh * 32 + nt * 8 + qid;
            bfr[nt][0] = __float_as_uint(x0[n]);
            bfr[nt][1] = __float_as_uint(x1[n]);
        }
#pragma unroll
        for (int nt = 0; nt < 4; ++nt)
            mma_tf32(acc[nt], afr, bfr[nt]);
    }
    __syncthreads();

#pragma unroll
    for (int dr = 0; dr < 2; ++dr) {
        int o = mw * 16 + qid + dr * 8;
        float bb = bias[o], ss = scale[o], tt = shift[o];
#pragma unroll
        for (int nt = 0; nt < 4; ++nt) {
            float v0 = fmaxf((acc[nt][dr * 2 + 0] + bb) * ss + tt, 0.0f);
            float v1 = fmaxf((acc[nt][dr * 2 + 1] + bb) * ss + tt, 0.0f);
            int n = nh * 32 + nt * 8 + qlane * 2;
            H1[o * STR + n + 0] = to_tf32(v0);
            H1[o * STR + n + 1] = to_tf32(v1);
        }
    }
}

// Layer 2: CIN=64, COUT=128, 64 cols. 8 warps x (M=16, N=64). Direct weight LDG.
__device__ __forceinline__ void mlp_layer2_mma(
    const float* __restrict__ bias,
    const float* __restrict__ scale,
    const float* __restrict__ shift,
    const float* H1, float* H2)
{
    const int tid   = threadIdx.x;
    const int wid   = tid >> 5;
    const int lane  = tid & 31;
    const int qid   = lane >> 2;
    const int qlane = lane & 3;

    float acc[8][4];
#pragma unroll
    for (int nt = 0; nt < 8; ++nt)
#pragma unroll
        for (int c = 0; c < 4; ++c) acc[nt][c] = 0.0f;

    const int m = wid * 16 + qid;

#pragma unroll
    for (int ks = 0; ks < 8; ++ks) {
        const int kb = ks * 8 + qlane;
        uint32_t afr[4];
        const float* w0 = g_Wt1 + kb * 128;
        const float* w1 = g_Wt1 + (kb + 4) * 128;
        afr[0] = __float_as_uint(w0[m]);
        afr[1] = __float_as_uint(w0[m + 8]);
        afr[2] = __float_as_uint(w1[m]);
        afr[3] = __float_as_uint(w1[m + 8]);
        uint32_t bfr[8][2];
        const float* h0 = H1 + kb * STR;
        const float* h1 = H1 + (kb + 4) * STR;
#pragma unroll
        for (int nt = 0; nt < 8; ++nt) {
            int n = nt * 8 + qid;
            bfr[nt][0] = __float_as_uint(h0[n]);
            bfr[nt][1] = __float_as_uint(h1[n]);
        }
#pragma unroll
        for (int nt = 0; nt < 8; ++nt)
            mma_tf32(acc[nt], afr, bfr[nt]);
    }
    __syncthreads();

#pragma unroll
    for (int dr = 0; dr < 2; ++dr) {
        int o = wid * 16 + qid + dr * 8;
        float bb = bias[o], ss = scale[o], tt = shift[o];
#pragma unroll
        for (int nt = 0; nt < 8; ++nt) {
            float v0 = fmaxf((acc[nt][dr * 2 + 0] + bb) * ss + tt, 0.0f);
            float v1 = fmaxf((acc[nt][dr * 2 + 1] + bb) * ss + tt, 0.0f);
            H2[o * STR + nt * 8 + qlane * 2 + 0] = to_tf32(v0);
            H2[o * STR + nt * 8 + qlane * 2 + 1] = to_tf32(v1);
        }
    }
    __syncthreads();
}

// Layer 3: CIN=128, COUT=256, 64 cols. 8 warps x (M=32, N=64). Direct weight LDG.
__device__ __forceinline__ void mlp_layer3_mma(
    const float* __restrict__ bias,
    const float* __restrict__ scale,
    const float* __restrict__ shift,
    const float* H2,
    float* __restrict__ outF, int b, int m0)
{
    const int tid   = threadIdx.x;
    const int wid   = tid >> 5;
    const int lane  = tid & 31;
    const int qid   = lane >> 2;
    const int qlane = lane & 3;

    float acc[2][8][4];
#pragma unroll
    for (int mt = 0; mt < 2; ++mt)
#pragma unroll
        for (int nt = 0; nt < 8; ++nt)
#pragma unroll
            for (int c = 0; c < 4; ++c) acc[mt][nt][c] = 0.0f;

#pragma unroll
    for (int ks = 0; ks < 16; ++ks) {
        const int kb = ks * 8 + qlane;
        uint32_t afr[2][4];
        const float* w0 = g_Wt2 + kb * 256;
        const float* w1 = g_Wt2 + (kb + 4) * 256;
#pragma unroll
        for (int mt = 0; mt < 2; ++mt) {
            int m = wid * 32 + mt * 16 + qid;
            afr[mt][0] = __float_as_uint(w0[m]);
            afr[mt][1] = __float_as_uint(w0[m + 8]);
            afr[mt][2] = __float_as_uint(w1[m]);
            afr[mt][3] = __float_as_uint(w1[m + 8]);
        }
        uint32_t bfr[8][2];
        const float* h0 = H2 + kb * STR;
        const float* h1 = H2 + (kb + 4) * STR;
#pragma unroll
        for (int nt = 0; nt < 8; ++nt) {
            int n = nt * 8 + qid;
            bfr[nt][0] = __float_as_uint(h0[n]);
            bfr[nt][1] = __float_as_uint(h1[n]);
        }
#pragma unroll
        for (int mt = 0; mt < 2; ++mt)
#pragma unroll
            for (int nt = 0; nt < 8; ++nt)
                mma_tf32(acc[mt][nt], afr[mt], bfr[nt]);
    }

#pragma unroll
    for (int mt = 0; mt < 2; ++mt) {
#pragma unroll
        for (int dr = 0; dr < 2; ++dr) {
            int o = wid * 32 + mt * 16 + qid + dr * 8;
            float bb = bias[o], ss = scale[o], tt = shift[o];
            float vA = 0.0f, vB = 0.0f;
#pragma unroll
            for (int nt = 0; nt < 8; ++nt) {
                float v0 = fmaxf((acc[mt][nt][dr * 2 + 0] + bb) * ss + tt, 0.0f);
                float v1 = fmaxf((acc[mt][nt][dr * 2 + 1] + bb) * ss + tt, 0.0f);
                float v  = fmaxf(v0, v1);
                if (nt < 4) vA = fmaxf(vA, v); else vB = fmaxf(vB, v);
            }
            vA = fmaxf(vA, __shfl_xor_sync(0xffffffffu, vA, 1));
            vA = fmaxf(vA, __shfl_xor_sync(0xffffffffu, vA, 2));
            vB = fmaxf(vB, __shfl_xor_sync(0xffffffffu, vB, 1));
            vB = fmaxf(vB, __shfl_xor_sync(0xffffffffu, vB, 2));
            if (qlane == 0) {
                outF[(b * 256 + o) * M_PTS + m0]     = vA;
                outF[(b * 256 + o) * M_PTS + m0 + 1] = vB;
            }
        }
    }
}

__global__ __launch_bounds__(256, 2) void mlp_kernel(
    const float* __restrict__ b0, const float* __restrict__ s0, const float* __restrict__ t0,
    const float* __restrict__ b1, const float* __restrict__ s1, const float* __restrict__ t1,
    const float* __restrict__ b2, const float* __restrict__ s2, const float* __restrict__ t2,
    float* __restrict__ outF)
{
    extern __shared__ float sm[];
    const int tid = threadIdx.x;
    const int b   = blockIdx.y;
    const int m0  = blockIdx.x * 2;

    // fold the flag reset for the NEXT launch into this kernel
    if (blockIdx.x == 0 && blockIdx.y == 0 && tid < BATCH + 1) {
        if (tid < BATCH) g_fps_progress[tid] = 0u;
        else g_prep_done = 0u;
    }

    int*   sIdx = (int*)(sm + OFF_SIDX);
    float* sCtr = sm + OFF_SCTR;

    if (tid < 64) sIdx[tid] = g_ball[b][m0 + (tid >> 5)][tid & 31];
    if (tid < 6)  sCtr[tid] = g_center[b][m0 + tid / 3][tid % 3];
    __syncthreads();

    {
        int col  = tid >> 2;
        int part = tid & 3;
        int p    = sIdx[col];
        int half = col >> 5;
        float cx = sCtr[half * 3 + 0];
        float cy = sCtr[half * 3 + 1];
        float cz = sCtr[half * 3 + 2];
        const float* fp = &g_featT[b][p][0];
#pragma unroll
        for (int jj = 0; jj < 18; ++jj) {
            int r = part * 18 + jj;
            float v;
            if (r == 0)      v = to_tf32(g_xyzT[b][0][p] - cx);
            else if (r == 1) v = to_tf32(g_xyzT[b][1][p] - cy);
            else if (r == 2) v = to_tf32(g_xyzT[b][2][p] - cz);
            else if (r < 67) v = to_tf32(fp[r - 3]);
            else             v = 0.0f;
            sm[OFF_XS + r * STR + col] = v;
        }
    }
    __syncthreads();

    mlp_layer1_mma(b0, s0, t0, sm + OFF_XS, sm + OFF_H1);
    __syncthreads();
    mlp_layer2_mma(b1, s1, t1, sm + OFF_H1, sm + OFF_H2);
    mlp_layer3_mma(b2, s2, t2, sm + OFF_H2, outF, b, m0);
}

// ======================= launch =======================
extern "C" void kernel_launch(void* const* d_in, const int* in_sizes, int n_in,
                              void* d_out, int out_size) {
    const float* xyz  = (const float*)d_in[0];
    const float* feat = (const float*)d_in[1];
    const float* W0 = (const float*)d_in[2];
    const float* b0 = (const float*)d_in[3];
    const float* s0 = (const float*)d_in[4];
    const float* t0 = (const float*)d_in[5];
    const float* W1 = (const float*)d_in[6];
    const float* b1 = (const float*)d_in[7];
    const float* s1 = (const float*)d_in[8];
    const float* t1 = (const float*)d_in[9];
    const float* W2 = (const float*)d_in[10];
    const float* b2 = (const float*)d_in[11];
    const float* s2 = (const float*)d_in[12];
    const float* t2 = (const float*)d_in[13];
    float* out = (float*)d_out;

    const int fps_smem = (3 * N_PTS + 128) * sizeof(float);
    const int mlp_smem = MLP_SMEM_FLOATS * sizeof(float);
    cudaFuncSetAttribute(fps_prep_kernel, cudaFuncAttributeMaxDynamicSharedMemorySize, fps_smem);
    cudaFuncSetAttribute(mlp_kernel, cudaFuncAttributeMaxDynamicSharedMemorySize, mlp_smem);

    fps_prep_kernel<<<BATCH + NPREP, 1024, fps_smem>>>(xyz, feat, W0, W1, W2, out);
    mlp_kernel<<<dim3(M_PTS / 2, BATCH), 256, mlp_smem>>>(
        b0, s0, t0, b1, s1, t1, b2, s2, t2, out + OUT_FEAT_OFF);
}